// round 2
// baseline (speedup 1.0000x reference)
#include <cuda_runtime.h>
#include <math.h>

#define Bb   2
#define Ss   4096
#define DIMd 768
#define Gg   256
#define Hh   4
#define DKk  64
#define SCALEf 0.125f

// ---------------- scratch (device globals: allocation-free) ----------------
__device__ float g_q[Bb * Ss * Gg];
__device__ float g_k[Bb * Ss * Gg];
__device__ float g_v[Bb * Ss * Gg];
__device__ float g_vw[Bb * Ss * Gg];
__device__ float g_att[Bb * Ss * Gg];
__device__ float g_p[(size_t)Bb * Hh * Ss * Ss];       // exp(scores), 536 MB
__device__ float g_part[Bb * Hh * 8 * Ss];             // partial column sums
__device__ float g_winv[Bb * Hh * Ss];                 // 1/denom per column

// ---------------------------------------------------------------------------
// Generic C[M,N] = A[M,K] @ W[N,K]^T + bias.  BM=BN=64, BK=16, 256 thr, 4x4.
// Used for QKV projections (A=x slice, lda=768) and out-proj (lda=256).
// M=8192, N=256, K=256 for all uses; grid = (N/64, M/64).
// ---------------------------------------------------------------------------
__global__ __launch_bounds__(256) void gemm_nt_bias_kernel(
    const float* __restrict__ A, int lda,
    const float* __restrict__ W,     // [N, K] row-major
    const float* __restrict__ bias,  // [N]
    float* __restrict__ C, int ldc, int K)
{
    __shared__ float As[16][68];
    __shared__ float Ws[16][68];
    const int tid = threadIdx.x;
    const int tx = tid & 15;         // n
    const int ty = tid >> 4;         // m
    const int m0 = blockIdx.y * 64;
    const int n0 = blockIdx.x * 64;

    const int r  = tid >> 2;         // 0..63
    const int kc = (tid & 3) * 4;    // 0,4,8,12

    float acc[4][4] = {};

    for (int k0 = 0; k0 < K; k0 += 16) {
        float4 a4 = *reinterpret_cast<const float4*>(&A[(size_t)(m0 + r) * lda + k0 + kc]);
        As[kc + 0][r] = a4.x; As[kc + 1][r] = a4.y;
        As[kc + 2][r] = a4.z; As[kc + 3][r] = a4.w;
        float4 w4 = *reinterpret_cast<const float4*>(&W[(size_t)(n0 + r) * K + k0 + kc]);
        Ws[kc + 0][r] = w4.x; Ws[kc + 1][r] = w4.y;
        Ws[kc + 2][r] = w4.z; Ws[kc + 3][r] = w4.w;
        __syncthreads();

        #pragma unroll
        for (int k = 0; k < 16; k++) {
            float4 av = *reinterpret_cast<const float4*>(&As[k][ty * 4]);
            float4 wv = *reinterpret_cast<const float4*>(&Ws[k][tx * 4]);
            float a[4] = {av.x, av.y, av.z, av.w};
            float w[4] = {wv.x, wv.y, wv.z, wv.w};
            #pragma unroll
            for (int i = 0; i < 4; i++)
                #pragma unroll
                for (int j = 0; j < 4; j++)
                    acc[i][j] += a[i] * w[j];
        }
        __syncthreads();
    }

    #pragma unroll
    for (int i = 0; i < 4; i++) {
        const int m = m0 + ty * 4 + i;
        const int nb = n0 + tx * 4;
        float4 o;
        o.x = acc[i][0] + bias[nb + 0];
        o.y = acc[i][1] + bias[nb + 1];
        o.z = acc[i][2] + bias[nb + 2];
        o.w = acc[i][3] + bias[nb + 3];
        *reinterpret_cast<float4*>(&C[(size_t)m * ldc + nb]) = o;
    }
}

// ---------------------------------------------------------------------------
// P[b,h,i,j] = exp(scale * q_i . k_j).  Per (b,h): M=N=4096, K=64.
// 128x128 tile, K=64 fully in SMEM, 256 threads, 8x8 per thread (split 4+4).
// Dynamic SMEM: 2 * 128*65*4 = 66560 B.
// grid = (32, 32, 8)
// ---------------------------------------------------------------------------
extern __shared__ float s_dyn[];
__global__ __launch_bounds__(256) void scores_exp_kernel(
    const float* __restrict__ Q,
    const float* __restrict__ Kmat,
    float* __restrict__ P)
{
    float (*Qs)[65] = reinterpret_cast<float(*)[65]>(s_dyn);
    float (*Ks)[65] = reinterpret_cast<float(*)[65]>(s_dyn + 128 * 65);

    const int tid = threadIdx.x;
    const int tx = tid & 15;
    const int ty = tid >> 4;
    const int bh = blockIdx.z;
    const int b = bh >> 2, h = bh & 3;
    const int i0 = blockIdx.y * 128;
    const int j0 = blockIdx.x * 128;

    const float* qbase = Q + ((size_t)(b * Ss + i0)) * Gg + h * DKk;
    const float* kbase = Kmat + ((size_t)(b * Ss + j0)) * Gg + h * DKk;

    const int dc = tx * 4;
    const int r0 = ty;
    #pragma unroll
    for (int it = 0; it < 8; it++) {
        const int r = r0 + it * 16;
        float4 q4 = *reinterpret_cast<const float4*>(qbase + (size_t)r * Gg + dc);
        Qs[r][dc + 0] = q4.x; Qs[r][dc + 1] = q4.y;
        Qs[r][dc + 2] = q4.z; Qs[r][dc + 3] = q4.w;
        float4 k4 = *reinterpret_cast<const float4*>(kbase + (size_t)r * Gg + dc);
        Ks[r][dc + 0] = k4.x; Ks[r][dc + 1] = k4.y;
        Ks[r][dc + 2] = k4.z; Ks[r][dc + 3] = k4.w;
    }
    __syncthreads();

    float acc[8][8] = {};
    #pragma unroll 16
    for (int d = 0; d < 64; d++) {
        float a[8], bb[8];
        #pragma unroll
        for (int c = 0; c < 4; c++) {
            a[c]      = Qs[ty * 4 + c][d];
            a[4 + c]  = Qs[64 + ty * 4 + c][d];
            bb[c]     = Ks[tx * 4 + c][d];
            bb[4 + c] = Ks[64 + tx * 4 + c][d];
        }
        #pragma unroll
        for (int i = 0; i < 8; i++)
            #pragma unroll
            for (int j = 0; j < 8; j++)
                acc[i][j] += a[i] * bb[j];
    }

    const size_t pbase = ((size_t)bh * Ss + i0) * Ss + j0;
    #pragma unroll
    for (int i = 0; i < 8; i++) {
        const int mi = (i < 4) ? (ty * 4 + i) : (64 + ty * 4 + (i - 4));
        float* prow = P + pbase + (size_t)mi * Ss;
        float4 o0, o1;
        o0.x = __expf(acc[i][0] * SCALEf);
        o0.y = __expf(acc[i][1] * SCALEf);
        o0.z = __expf(acc[i][2] * SCALEf);
        o0.w = __expf(acc[i][3] * SCALEf);
        o1.x = __expf(acc[i][4] * SCALEf);
        o1.y = __expf(acc[i][5] * SCALEf);
        o1.z = __expf(acc[i][6] * SCALEf);
        o1.w = __expf(acc[i][7] * SCALEf);
        *reinterpret_cast<float4*>(&prow[tx * 4])      = o0;
        *reinterpret_cast<float4*>(&prow[64 + tx * 4]) = o1;
    }
}

// ---------------------------------------------------------------------------
// Partial column sums over i: part[bh, ic, j] = sum_{i in chunk} P[bh, i, j]
// grid = (16, 8, 8); each thread owns one column j within a 512-row chunk.
// ---------------------------------------------------------------------------
__global__ __launch_bounds__(256) void colsum_part_kernel(
    const float* __restrict__ P, float* __restrict__ part)
{
    const int j  = blockIdx.x * 256 + threadIdx.x;
    const int ic = blockIdx.y;
    const int bh = blockIdx.z;
    const float* p = P + (size_t)bh * Ss * Ss + (size_t)ic * 512 * Ss + j;
    float s0 = 0.f, s1 = 0.f, s2 = 0.f, s3 = 0.f;
    for (int i = 0; i < 512; i += 4) {
        s0 += p[0];
        s1 += p[(size_t)Ss];
        s2 += p[(size_t)2 * Ss];
        s3 += p[(size_t)3 * Ss];
        p += (size_t)4 * Ss;
    }
    part[((bh << 3) + ic) * Ss + j] = (s0 + s1) + (s2 + s3);
}

// winv[bh, j] = 1 / sum_c part[bh, c, j].   grid = 128 x 256 threads
__global__ __launch_bounds__(256) void colsum_final_kernel(
    const float* __restrict__ part, float* __restrict__ winv)
{
    const int idx = blockIdx.x * 256 + threadIdx.x;   // bh*Ss + j
    const int bh = idx >> 12;
    const int j  = idx & (Ss - 1);
    float s = 0.f;
    #pragma unroll
    for (int c = 0; c < 8; c++)
        s += part[((bh << 3) + c) * Ss + j];
    winv[idx] = 1.0f / s;
}

// vw[b,j,h,d] = v[b,j,h,d] * winv[b,h,j].   grid = 8192 x 256 threads
__global__ __launch_bounds__(256) void scale_v_kernel(
    const float* __restrict__ v, const float* __restrict__ winv,
    float* __restrict__ vw)
{
    const int idx = blockIdx.x * 256 + threadIdx.x;    // < B*S*G = 2^21
    const int b    = idx >> 20;                        // Ss*Gg = 2^20
    const int srow = (idx >> 8) & (Ss - 1);
    const int h    = (idx >> 6) & 3;
    vw[idx] = v[idx] * winv[((b << 2) + h) * Ss + srow];
}

// ---------------------------------------------------------------------------
// Att[b,i,h,d] = sum_j P[bh,i,j] * vw[b,j,h,d].  Per (b,h): M=4096,N=64,K=4096
// BM=128, BN=64, BK=16, 256 threads, 8x4 per thread.  grid = (32, 8)
// ---------------------------------------------------------------------------
__global__ __launch_bounds__(256) void pv_kernel(
    const float* __restrict__ P,
    const float* __restrict__ Vw,
    float* __restrict__ Att)
{
    __shared__ float Ps[16][132];
    __shared__ float Vs[16][68];

    const int tid = threadIdx.x;
    const int tx = tid & 15;
    const int ty = tid >> 4;
    const int bh = blockIdx.y;
    const int b = bh >> 2, h = bh & 3;
    const int i0 = blockIdx.x * 128;

    const float* pbase = P + ((size_t)bh * Ss + i0) * Ss;
    const float* vbase = Vw + (size_t)b * Ss * Gg + h * DKk;

    float acc[8][4] = {};

    const int pkc = (tid & 3) * 4;   // 0,4,8,12
    const int pr  = tid >> 2;        // 0..63
    const int vr  = tid >> 4;        // 0..15
    const int vc  = (tid & 15) * 4;  // 0..60

    for (int k0 = 0; k0 < Ss; k0 += 16) {
        #pragma unroll
        for (int it = 0; it < 2; it++) {
            const int rr = pr + it * 64;
            float4 p4 = *reinterpret_cast<const float4*>(pbase + (size_t)rr * Ss + k0 + pkc);
            Ps[pkc + 0][rr] = p4.x; Ps[pkc + 1][rr] = p4.y;
            Ps[pkc + 2][rr] = p4.z; Ps[pkc + 3][rr] = p4.w;
        }
        float4 v4 = *reinterpret_cast<const float4*>(vbase + (size_t)(k0 + vr) * Gg + vc);
        Vs[vr][vc + 0] = v4.x; Vs[vr][vc + 1] = v4.y;
        Vs[vr][vc + 2] = v4.z; Vs[vr][vc + 3] = v4.w;
        __syncthreads();

        #pragma unroll
        for (int k = 0; k < 16; k++) {
            float4 a0 = *reinterpret_cast<const float4*>(&Ps[k][ty * 4]);
            float4 a1 = *reinterpret_cast<const float4*>(&Ps[k][64 + ty * 4]);
            float4 b4 = *reinterpret_cast<const float4*>(&Vs[k][tx * 4]);
            float a[8] = {a0.x, a0.y, a0.z, a0.w, a1.x, a1.y, a1.z, a1.w};
            float bb[4] = {b4.x, b4.y, b4.z, b4.w};
            #pragma unroll
            for (int i = 0; i < 8; i++)
                #pragma unroll
                for (int j = 0; j < 4; j++)
                    acc[i][j] += a[i] * bb[j];
        }
        __syncthreads();
    }

    #pragma unroll
    for (int i = 0; i < 8; i++) {
        const int mi = (i < 4) ? (ty * 4 + i) : (64 + ty * 4 + (i - 4));
        float4 o;
        o.x = acc[i][0]; o.y = acc[i][1]; o.z = acc[i][2]; o.w = acc[i][3];
        *reinterpret_cast<float4*>(
            &Att[((size_t)(b * Ss + i0 + mi)) * Gg + h * DKk + tx * 4]) = o;
    }
}

// ---------------------------------------------------------------------------
extern "C" void kernel_launch(void* const* d_in, const int* in_sizes, int n_in,
                              void* d_out, int out_size)
{
    const float* x  = (const float*)d_in[0];
    const float* wq = (const float*)d_in[1];
    const float* bq = (const float*)d_in[2];
    const float* wk = (const float*)d_in[3];
    const float* bk = (const float*)d_in[4];
    const float* wv = (const float*)d_in[5];
    const float* bv = (const float*)d_in[6];
    const float* wo = (const float*)d_in[7];
    const float* bo = (const float*)d_in[8];
    float* out = (float*)d_out;

    float *q, *k, *v, *vw, *att, *p, *part, *winv;
    cudaGetSymbolAddress((void**)&q,    g_q);
    cudaGetSymbolAddress((void**)&k,    g_k);
    cudaGetSymbolAddress((void**)&v,    g_v);
    cudaGetSymbolAddress((void**)&vw,   g_vw);
    cudaGetSymbolAddress((void**)&att,  g_att);
    cudaGetSymbolAddress((void**)&p,    g_p);
    cudaGetSymbolAddress((void**)&part, g_part);
    cudaGetSymbolAddress((void**)&winv, g_winv);

    const int SCORES_SMEM = 2 * 128 * 65 * 4;   // 66560 B
    cudaFuncSetAttribute(scores_exp_kernel,
                         cudaFuncAttributeMaxDynamicSharedMemorySize, SCORES_SMEM);

    dim3 gProj(4, 128);   // N/64, M/64 for M=8192, N=256

    // 1) QKV projections
    gemm_nt_bias_kernel<<<gProj, 256>>>(x,          DIMd, wq, bq, q, Gg, Gg);
    gemm_nt_bias_kernel<<<gProj, 256>>>(x + Gg,     DIMd, wk, bk, k, Gg, Gg);
    gemm_nt_bias_kernel<<<gProj, 256>>>(x + 2 * Gg, DIMd, wv, bv, v, Gg, Gg);

    // 2) P = exp(scale * Q K^T)
    scores_exp_kernel<<<dim3(32, 32, 8), 256, SCORES_SMEM>>>(q, k, p);

    // 3) column sums over i -> winv
    colsum_part_kernel<<<dim3(16, 8, 8), 256>>>(p, part);
    colsum_final_kernel<<<128, 256>>>(part, winv);

    // 4) vw = v * winv
    scale_v_kernel<<<8192, 256>>>(v, winv, vw);

    // 5) Att = P @ vw
    pv_kernel<<<dim3(32, 8), 256>>>(p, vw, att);

    // 6) out = Att @ wo^T + bo
    gemm_nt_bias_kernel<<<gProj, 256>>>(att, Gg, wo, bo, out, Gg, Gg);
}

// round 4
// speedup vs baseline: 1.7548x; 1.7548x over previous
#include <cuda_runtime.h>
#include <cuda_bf16.h>
#include <math.h>

#define Bb   2
#define Ss   4096
#define Gg   256
#define Hh   4
#define DKk  64
#define DIMd 768
#define EXP2K (0.125f * 1.44269504088896341f)

// ---------------- scratch ----------------
__device__ __nv_bfloat16 g_qhi[Bb * Ss * Gg];
__device__ __nv_bfloat16 g_qlo[Bb * Ss * Gg];
__device__ __nv_bfloat16 g_khi[Bb * Ss * Gg];
__device__ __nv_bfloat16 g_klo[Bb * Ss * Gg];
__device__ float         g_v  [Bb * Ss * Gg];
__device__ __nv_bfloat16 g_phi[(size_t)Bb * Hh * Ss * Ss];
__device__ __nv_bfloat16 g_plo[(size_t)Bb * Hh * Ss * Ss];
__device__ float g_part[(size_t)Bb * Hh * 64 * Ss];
__device__ float g_winv[Bb * Hh * Ss];
__device__ __nv_bfloat16 g_vthi[Bb * Hh * DKk * Ss];
__device__ __nv_bfloat16 g_vtlo[Bb * Hh * DKk * Ss];
__device__ float g_att[Bb * Ss * Gg];

// ---------------- helpers ----------------
__device__ __forceinline__ unsigned smem_u32(const void* p) {
    unsigned a;
    asm("{ .reg .u64 t; cvta.to.shared.u64 t, %1; cvt.u32.u64 %0, t; }" : "=r"(a) : "l"(p));
    return a;
}
__device__ __forceinline__ float ex2f(float x) {
    float r;
    asm("ex2.approx.ftz.f32 %0, %1;" : "=f"(r) : "f"(x));
    return r;
}
__device__ __forceinline__ void ldsm4(unsigned& r0, unsigned& r1, unsigned& r2,
                                      unsigned& r3, unsigned addr) {
    asm volatile("ldmatrix.sync.aligned.m8n8.x4.shared.b16 {%0,%1,%2,%3}, [%4];"
                 : "=r"(r0), "=r"(r1), "=r"(r2), "=r"(r3) : "r"(addr));
}
__device__ __forceinline__ void mma_bf16(float* c, const unsigned* a, const unsigned* b) {
    asm volatile(
        "mma.sync.aligned.m16n8k16.row.col.f32.bf16.bf16.f32 "
        "{%0,%1,%2,%3},{%4,%5,%6,%7},{%8,%9},{%0,%1,%2,%3};"
        : "+f"(c[0]), "+f"(c[1]), "+f"(c[2]), "+f"(c[3])
        : "r"(a[0]), "r"(a[1]), "r"(a[2]), "r"(a[3]), "r"(b[0]), "r"(b[1]));
}

// ---------------- fp32 projection GEMM (+ optional bf16 hi/lo split out) ----
template <int SPLIT>
__device__ __forceinline__ void gemm_body(
    const float* __restrict__ A, int lda, const float* __restrict__ W,
    const float* __restrict__ bias, float* __restrict__ C,
    __nv_bfloat16* __restrict__ Chi, __nv_bfloat16* __restrict__ Clo, int K)
{
    __shared__ float As[16][68];
    __shared__ float Ws[16][68];
    const int tid = threadIdx.x, tx = tid & 15, ty = tid >> 4;
    const int m0 = blockIdx.y * 64, n0 = blockIdx.x * 64;
    const int r = tid >> 2, kc = (tid & 3) * 4;
    float acc[4][4] = {};
    for (int k0 = 0; k0 < K; k0 += 16) {
        float4 a4 = *reinterpret_cast<const float4*>(&A[(size_t)(m0 + r) * lda + k0 + kc]);
        As[kc][r] = a4.x; As[kc+1][r] = a4.y; As[kc+2][r] = a4.z; As[kc+3][r] = a4.w;
        float4 w4 = *reinterpret_cast<const float4*>(&W[(size_t)(n0 + r) * K + k0 + kc]);
        Ws[kc][r] = w4.x; Ws[kc+1][r] = w4.y; Ws[kc+2][r] = w4.z; Ws[kc+3][r] = w4.w;
        __syncthreads();
        #pragma unroll
        for (int k = 0; k < 16; k++) {
            float4 av = *reinterpret_cast<const float4*>(&As[k][ty * 4]);
            float4 wv = *reinterpret_cast<const float4*>(&Ws[k][tx * 4]);
            float a[4] = {av.x, av.y, av.z, av.w}, w[4] = {wv.x, wv.y, wv.z, wv.w};
            #pragma unroll
            for (int i = 0; i < 4; i++)
                #pragma unroll
                for (int j = 0; j < 4; j++) acc[i][j] += a[i] * w[j];
        }
        __syncthreads();
    }
    #pragma unroll
    for (int i = 0; i < 4; i++) {
        const int m = m0 + ty * 4 + i, nb = n0 + tx * 4;
        float o[4];
        #pragma unroll
        for (int j = 0; j < 4; j++) o[j] = acc[i][j] + bias[nb + j];
        if (SPLIT) {
            __nv_bfloat162 h01 = __floats2bfloat162_rn(o[0], o[1]);
            __nv_bfloat162 h23 = __floats2bfloat162_rn(o[2], o[3]);
            __nv_bfloat162 l01 = __floats2bfloat162_rn(o[0]-__bfloat162float(h01.x), o[1]-__bfloat162float(h01.y));
            __nv_bfloat162 l23 = __floats2bfloat162_rn(o[2]-__bfloat162float(h23.x), o[3]-__bfloat162float(h23.y));
            uint2 hv, lv;
            hv.x = *(unsigned*)&h01; hv.y = *(unsigned*)&h23;
            lv.x = *(unsigned*)&l01; lv.y = *(unsigned*)&l23;
            *reinterpret_cast<uint2*>(&Chi[(size_t)m * Gg + nb]) = hv;
            *reinterpret_cast<uint2*>(&Clo[(size_t)m * Gg + nb]) = lv;
        } else {
            *reinterpret_cast<float4*>(&C[(size_t)m * Gg + nb]) = make_float4(o[0], o[1], o[2], o[3]);
        }
    }
}
__global__ __launch_bounds__(256) void gemm_f32_kernel(
    const float* __restrict__ A, int lda, const float* __restrict__ W,
    const float* __restrict__ bias, float* __restrict__ C, int K)
{ gemm_body<0>(A, lda, W, bias, C, nullptr, nullptr, K); }

__global__ __launch_bounds__(256) void gemm_split_kernel(
    const float* __restrict__ A, int lda, const float* __restrict__ W,
    const float* __restrict__ bias, __nv_bfloat16* __restrict__ Chi,
    __nv_bfloat16* __restrict__ Clo, int K)
{ gemm_body<1>(A, lda, W, bias, nullptr, Chi, Clo, K); }

// ---------------------------------------------------------------------------
// scores: P = exp(scale*QK^T) via mma.sync bf16x3. CTA tile 128x128, K=64.
// 8 warps as 2(m) x 4(n), warp tile 64x32. grid (32,32,8), 256 thr.
// dyn smem = 4 * 128*72*2 = 73728 B (Qhi, Qlo, Khi, Klo padded rows 144B).
// Fused deterministic column partial sums -> part.
// ---------------------------------------------------------------------------
__global__ __launch_bounds__(256) void scores_wm_kernel(
    const __nv_bfloat16* __restrict__ qhi, const __nv_bfloat16* __restrict__ qlo,
    const __nv_bfloat16* __restrict__ khi, const __nv_bfloat16* __restrict__ klo,
    __nv_bfloat16* __restrict__ Phi, __nv_bfloat16* __restrict__ Plo,
    float* __restrict__ part)
{
    extern __shared__ char sm[];
    const int QH = 0, QL = 18432, KH = 36864, KL = 55296;
    const int tid = threadIdx.x, lane = tid & 31, wid = tid >> 5;
    const int wm = wid >> 2, wn = wid & 3;
    const int bh = blockIdx.z, b = bh >> 2, h = bh & 3;
    const int i0 = blockIdx.y * 128, j0 = blockIdx.x * 128;

    {   // load 4 operand tiles: thread = half a row (64B) of each
        const int row = tid >> 1, half = tid & 1;
        const size_t qoff = ((size_t)(b * Ss + i0 + row)) * Gg + h * DKk + half * 32;
        const size_t koff = ((size_t)(b * Ss + j0 + row)) * Gg + h * DKk + half * 32;
        const unsigned so = row * 144 + half * 64;
        const uint4* q1 = reinterpret_cast<const uint4*>(qhi + qoff);
        const uint4* q2 = reinterpret_cast<const uint4*>(qlo + qoff);
        const uint4* k1 = reinterpret_cast<const uint4*>(khi + koff);
        const uint4* k2 = reinterpret_cast<const uint4*>(klo + koff);
        #pragma unroll
        for (int u = 0; u < 4; u++) {
            *reinterpret_cast<uint4*>(sm + QH + so + u * 16) = q1[u];
            *reinterpret_cast<uint4*>(sm + QL + so + u * 16) = q2[u];
            *reinterpret_cast<uint4*>(sm + KH + so + u * 16) = k1[u];
            *reinterpret_cast<uint4*>(sm + KL + so + u * 16) = k2[u];
        }
    }
    __syncthreads();

    const unsigned base = smem_u32(sm);
    const int qr = lane >> 2, qc = lane & 3;
    // ldmatrix lane address components (A: rows m, B: rows n; both k-major rows)
    const unsigned aoff = (wm * 64 + (lane & 15)) * 144 + ((lane >> 4) * 8) * 2;
    const unsigned boff = (wn * 32 + ((lane >> 4) & 1) * 8 + (lane & 7)) * 144
                        + (((lane >> 3) & 1) * 8) * 2;

    float acc[4][4][4] = {};
    #pragma unroll
    for (int kk = 0; kk < 4; kk++) {
        unsigned aH[4][4], aL[4][4], bH[2][4], bL[2][4];
        #pragma unroll
        for (int mt = 0; mt < 4; mt++) {
            const unsigned ad = base + QH + aoff + mt * 2304 + kk * 32;
            ldsm4(aH[mt][0], aH[mt][1], aH[mt][2], aH[mt][3], ad);
            ldsm4(aL[mt][0], aL[mt][1], aL[mt][2], aL[mt][3], ad + (QL - QH));
        }
        #pragma unroll
        for (int g = 0; g < 2; g++) {
            const unsigned bd = base + KH + boff + g * 2304 + kk * 32;
            ldsm4(bH[g][0], bH[g][1], bH[g][2], bH[g][3], bd);
            ldsm4(bL[g][0], bL[g][1], bL[g][2], bL[g][3], bd + (KL - KH));
        }
        #pragma unroll
        for (int mt = 0; mt < 4; mt++)
            #pragma unroll
            for (int nt = 0; nt < 4; nt++) {
                const unsigned* pbh = &bH[nt >> 1][(nt & 1) * 2];
                const unsigned* pbl = &bL[nt >> 1][(nt & 1) * 2];
                mma_bf16(acc[mt][nt], aH[mt], pbh);
                mma_bf16(acc[mt][nt], aH[mt], pbl);
                mma_bf16(acc[mt][nt], aL[mt], pbh);
            }
    }

    // exp (in place)
    #pragma unroll
    for (int mt = 0; mt < 4; mt++)
        #pragma unroll
        for (int nt = 0; nt < 4; nt++)
            #pragma unroll
            for (int r = 0; r < 4; r++)
                acc[mt][nt][r] = ex2f(acc[mt][nt][r] * EXP2K);

    // deterministic column partial sums: reduce over 64 rows of this warp tile
    const int jbase = j0 + wn * 32;
    #pragma unroll
    for (int nt = 0; nt < 4; nt++) {
        #pragma unroll
        for (int p = 0; p < 2; p++) {
            float s = 0.f;
            #pragma unroll
            for (int mt = 0; mt < 4; mt++) s += acc[mt][nt][p] + acc[mt][nt][p + 2];
            #pragma unroll
            for (int o = 4; o < 32; o <<= 1) s += __shfl_xor_sync(0xffffffffu, s, o);
            if (qr == 0)
                part[((size_t)(bh * 32 + blockIdx.y) * 2 + wm) * Ss
                     + jbase + nt * 8 + qc * 2 + p] = s;
        }
    }

    // store P (bf16 hi/lo pairs) straight from fragments
    #pragma unroll
    for (int mt = 0; mt < 4; mt++) {
        const int row0 = i0 + wm * 64 + mt * 16 + qr;
        #pragma unroll
        for (int nt = 0; nt < 4; nt++) {
            const int col = jbase + nt * 8 + qc * 2;
            #pragma unroll
            for (int pr = 0; pr < 2; pr++) {
                const float e0 = acc[mt][nt][pr * 2 + 0];
                const float e1 = acc[mt][nt][pr * 2 + 1];
                __nv_bfloat162 h2 = __floats2bfloat162_rn(e0, e1);
                __nv_bfloat162 l2 = __floats2bfloat162_rn(e0 - __bfloat162float(h2.x),
                                                          e1 - __bfloat162float(h2.y));
                const size_t off = ((size_t)bh * Ss + row0 + pr * 8) * Ss + col;
                *reinterpret_cast<__nv_bfloat162*>(Phi + off) = h2;
                *reinterpret_cast<__nv_bfloat162*>(Plo + off) = l2;
            }
        }
    }
}

// winv[bh,j] = 1/sum_{c<64} part[bh*64+c, j].  grid (16,8) x 256
__global__ __launch_bounds__(256) void colsum_final_kernel(
    const float* __restrict__ part, float* __restrict__ winv)
{
    const int j = blockIdx.x * 256 + threadIdx.x;
    const int bh = blockIdx.y;
    const float* p = part + (size_t)bh * 64 * Ss + j;
    float s = 0.f;
    #pragma unroll 8
    for (int c = 0; c < 64; c++) s += p[(size_t)c * Ss];
    winv[(size_t)bh * Ss + j] = 1.0f / s;
}

// vT[bh,d,j] = v[b,j,h*64+d]*winv[bh,j] -> bf16 hi/lo. grid (64,8) x 256
__global__ __launch_bounds__(256) void scale_v_t_kernel(
    const float* __restrict__ v, const float* __restrict__ winv,
    __nv_bfloat16* __restrict__ tH, __nv_bfloat16* __restrict__ tL)
{
    __shared__ float ts[64][65];
    const int tid = threadIdx.x, bh = blockIdx.y, b = bh >> 2, h = bh & 3;
    const int j0 = blockIdx.x * 64;
    {
        const int j = tid >> 2, c0 = (tid & 3) * 16;
        const float* src = v + ((size_t)(b * Ss + j0 + j)) * Gg + h * DKk + c0;
        #pragma unroll
        for (int u = 0; u < 4; u++) {
            float4 f = *reinterpret_cast<const float4*>(src + u * 4);
            ts[j][c0 + 4*u]     = f.x; ts[j][c0 + 4*u + 1] = f.y;
            ts[j][c0 + 4*u + 2] = f.z; ts[j][c0 + 4*u + 3] = f.w;
        }
    }
    __syncthreads();
    const int d = tid >> 2, jj0 = (tid & 3) * 16;
    const size_t ob = (((size_t)bh) * DKk + d) * Ss + j0 + jj0;
    const float* wv = winv + (size_t)bh * Ss + j0 + jj0;
    __nv_bfloat16 hbuf[16], lbuf[16];
    #pragma unroll
    for (int u = 0; u < 16; u++) {
        float f = ts[jj0 + u][d] * wv[u];
        __nv_bfloat16 hb = __float2bfloat16(f);
        hbuf[u] = hb; lbuf[u] = __float2bfloat16(f - __bfloat162float(hb));
    }
    #pragma unroll
    for (int u = 0; u < 2; u++) {
        *reinterpret_cast<uint4*>(tH + ob + u * 8) = reinterpret_cast<uint4*>(hbuf)[u];
        *reinterpret_cast<uint4*>(tL + ob + u * 8) = reinterpret_cast<uint4*>(lbuf)[u];
    }
}

// ---------------------------------------------------------------------------
// pv: Att = P @ Vw^T via mma.sync bf16x3.  CTA 128x64, K=4096 (64 chunks of 64).
// 8 warps as 4(m) x 2(n), warp tile 32x32.  grid (32,8), 256 thr.
// dyn smem = 2*128*144 + 2*64*144 = 55296 B.  Register-prefetch pipeline.
// ---------------------------------------------------------------------------
__global__ __launch_bounds__(256) void pv_wm_kernel(
    const __nv_bfloat16* __restrict__ Phi, const __nv_bfloat16* __restrict__ Plo,
    const __nv_bfloat16* __restrict__ vthi, const __nv_bfloat16* __restrict__ vtlo,
    float* __restrict__ att)
{
    extern __shared__ char sm[];
    const int PH = 0, PL = 18432, VH = 36864, VL = 46080;
    const int tid = threadIdx.x, lane = tid & 31, wid = tid >> 5;
    const int wm = wid >> 1, wn = wid & 1;
    const int bh = blockIdx.y, b = bh >> 2, h = bh & 3;
    const int i0 = blockIdx.x * 128;
    const int qr = lane >> 2, qc = lane & 3;

    const int prow = tid >> 1, phalf = tid & 1;
    const __nv_bfloat16* pHs = Phi + ((size_t)bh * Ss + i0 + prow) * Ss + phalf * 32;
    const __nv_bfloat16* pLs = Plo + ((size_t)bh * Ss + i0 + prow) * Ss + phalf * 32;
    const int vrow = tid >> 2, vq = tid & 3;
    const __nv_bfloat16* vHs = vthi + ((size_t)bh * DKk + vrow) * Ss + vq * 16;
    const __nv_bfloat16* vLs = vtlo + ((size_t)bh * DKk + vrow) * Ss + vq * 16;
    const unsigned pso = prow * 144 + phalf * 64;
    const unsigned vso = vrow * 144 + vq * 32;

    const unsigned base = smem_u32(sm);
    const unsigned aoff = (wm * 32 + (lane & 15)) * 144 + ((lane >> 4) * 8) * 2;
    const unsigned boff = (wn * 32 + ((lane >> 4) & 1) * 8 + (lane & 7)) * 144
                        + (((lane >> 3) & 1) * 8) * 2;

    float acc[2][4][4] = {};
    uint4 rp[4], rl[4], rv[2], rw[2];

    // prologue prefetch chunk 0
    #pragma unroll
    for (int u = 0; u < 4; u++) {
        rp[u] = reinterpret_cast<const uint4*>(pHs)[u];
        rl[u] = reinterpret_cast<const uint4*>(pLs)[u];
    }
    rv[0] = reinterpret_cast<const uint4*>(vHs)[0];
    rv[1] = reinterpret_cast<const uint4*>(vHs)[1];
    rw[0] = reinterpret_cast<const uint4*>(vLs)[0];
    rw[1] = reinterpret_cast<const uint4*>(vLs)[1];

    for (int c = 0; c < 64; c++) {
        #pragma unroll
        for (int u = 0; u < 4; u++) {
            *reinterpret_cast<uint4*>(sm + PH + pso + u * 16) = rp[u];
            *reinterpret_cast<uint4*>(sm + PL + pso + u * 16) = rl[u];
        }
        *reinterpret_cast<uint4*>(sm + VH + vso)      = rv[0];
        *reinterpret_cast<uint4*>(sm + VH + vso + 16) = rv[1];
        *reinterpret_cast<uint4*>(sm + VL + vso)      = rw[0];
        *reinterpret_cast<uint4*>(sm + VL + vso + 16) = rw[1];
        __syncthreads();

        if (c < 63) {   // prefetch next chunk (overlaps with MMA below)
            const size_t go = (size_t)(c + 1) * 64;
            #pragma unroll
            for (int u = 0; u < 4; u++) {
                rp[u] = reinterpret_cast<const uint4*>(pHs + go)[u];
                rl[u] = reinterpret_cast<const uint4*>(pLs + go)[u];
            }
            rv[0] = reinterpret_cast<const uint4*>(vHs + go)[0];
            rv[1] = reinterpret_cast<const uint4*>(vHs + go)[1];
            rw[0] = reinterpret_cast<const uint4*>(vLs + go)[0];
            rw[1] = reinterpret_cast<const uint4*>(vLs + go)[1];
        }

        #pragma unroll
        for (int kk = 0; kk < 4; kk++) {
            unsigned aH[2][4], aL[2][4], bH[2][4], bL[2][4];
            #pragma unroll
            for (int mt = 0; mt < 2; mt++) {
                const unsigned ad = base + PH + aoff + mt * 2304 + kk * 32;
                ldsm4(aH[mt][0], aH[mt][1], aH[mt][2], aH[mt][3], ad);
                ldsm4(aL[mt][0], aL[mt][1], aL[mt][2], aL[mt][3], ad + (PL - PH));
            }
            #pragma unroll
            for (int g = 0; g < 2; g++) {
                const unsigned bd = base + VH + boff + g * 2304 + kk * 32;
                ldsm4(bH[g][0], bH[g][1], bH[g][2], bH[g][3], bd);
                ldsm4(bL[g][0], bL[g][1], bL[g][2], bL[g][3], bd + (VL - VH));
            }
            #pragma unroll
            for (int mt = 0; mt < 2; mt++)
                #pragma unroll
                for (int nt = 0; nt < 4; nt++) {
                    const unsigned* pbh = &bH[nt >> 1][(nt & 1) * 2];
                    const unsigned* pbl = &bL[nt >> 1][(nt & 1) * 2];
                    mma_bf16(acc[mt][nt], aH[mt], pbh);
                    mma_bf16(acc[mt][nt], aH[mt], pbl);
                    mma_bf16(acc[mt][nt], aL[mt], pbh);
                }
        }
        __syncthreads();
    }

    // store Att fragments (f32, pairs of consecutive d)
    #pragma unroll
    for (int mt = 0; mt < 2; mt++) {
        const int row0 = i0 + wm * 32 + mt * 16 + qr;
        #pragma unroll
        for (int nt = 0; nt < 4; nt++) {
            const int col = h * DKk + wn * 32 + nt * 8 + qc * 2;
            #pragma unroll
            for (int pr = 0; pr < 2; pr++) {
                float2 o = make_float2(acc[mt][nt][pr * 2], acc[mt][nt][pr * 2 + 1]);
                *reinterpret_cast<float2*>(
                    att + ((size_t)(b * Ss + row0 + pr * 8)) * Gg + col) = o;
            }
        }
    }
}

// ---------------------------------------------------------------------------
extern "C" void kernel_launch(void* const* d_in, const int* in_sizes, int n_in,
                              void* d_out, int out_size)
{
    const float* x  = (const float*)d_in[0];
    const float* wq = (const float*)d_in[1];
    const float* bq = (const float*)d_in[2];
    const float* wk = (const float*)d_in[3];
    const float* bk = (const float*)d_in[4];
    const float* wv = (const float*)d_in[5];
    const float* bv = (const float*)d_in[6];
    const float* wo = (const float*)d_in[7];
    const float* bo = (const float*)d_in[8];
    float* out = (float*)d_out;

    __nv_bfloat16 *qhi, *qlo, *khi, *klo, *phi, *plo, *vthi, *vtlo;
    float *v, *part, *winv, *att;
    cudaGetSymbolAddress((void**)&qhi, g_qhi);  cudaGetSymbolAddress((void**)&qlo, g_qlo);
    cudaGetSymbolAddress((void**)&khi, g_khi);  cudaGetSymbolAddress((void**)&klo, g_klo);
    cudaGetSymbolAddress((void**)&v,   g_v);
    cudaGetSymbolAddress((void**)&phi, g_phi);  cudaGetSymbolAddress((void**)&plo, g_plo);
    cudaGetSymbolAddress((void**)&part,g_part); cudaGetSymbolAddress((void**)&winv,g_winv);
    cudaGetSymbolAddress((void**)&vthi,g_vthi); cudaGetSymbolAddress((void**)&vtlo,g_vtlo);
    cudaGetSymbolAddress((void**)&att, g_att);

    const int SC_SMEM = 73728;
    const int PV_SMEM = 55296;
    cudaFuncSetAttribute(scores_wm_kernel, cudaFuncAttributeMaxDynamicSharedMemorySize, SC_SMEM);
    cudaFuncSetAttribute(pv_wm_kernel,     cudaFuncAttributeMaxDynamicSharedMemorySize, PV_SMEM);

    dim3 gProj(4, 128);
    gemm_split_kernel<<<gProj, 256>>>(x,          DIMd, wq, bq, qhi, qlo, Gg);
    gemm_split_kernel<<<gProj, 256>>>(x + Gg,     DIMd, wk, bk, khi, klo, Gg);
    gemm_f32_kernel  <<<gProj, 256>>>(x + 2 * Gg, DIMd, wv, bv, v, Gg);

    scores_wm_kernel<<<dim3(32, 32, 8), 256, SC_SMEM>>>(qhi, qlo, khi, klo, phi, plo, part);
    colsum_final_kernel<<<dim3(16, 8), 256>>>(part, winv);
    scale_v_t_kernel<<<dim3(64, 8), 256>>>(v, winv, vthi, vtlo);
    pv_wm_kernel<<<dim3(32, 8), 256, PV_SMEM>>>(phi, plo, vthi, vtlo, att);

    gemm_f32_kernel<<<gProj, 256>>>(att, Gg, wo, bo, out, Gg);
}

// round 6
// speedup vs baseline: 2.3362x; 1.3314x over previous
#include <cuda_runtime.h>
#include <cuda_bf16.h>
#include <cuda_fp16.h>
#include <math.h>

#define Bb   2
#define Ss   4096
#define Gg   256
#define Hh   4
#define DKk  64
#define DIMd 768
#define EXP2K (0.125f * 1.44269504088896341f)
#define VSCALE 4096.0f
#define OSCALE (1.0f / 4096.0f)

// ---------------- scratch ----------------
__device__ __nv_bfloat16 g_qhi[Bb * Ss * Gg];
__device__ __nv_bfloat16 g_qlo[Bb * Ss * Gg];
__device__ __nv_bfloat16 g_khi[Bb * Ss * Gg];
__device__ __nv_bfloat16 g_klo[Bb * Ss * Gg];
__device__ float         g_v  [Bb * Ss * Gg];
__device__ __half g_p[(size_t)Bb * Hh * Ss * Ss];            // 268 MB, fp16
__device__ float g_part[(size_t)Bb * Hh * 64 * Ss];
__device__ float g_winv[Bb * Hh * Ss];
__device__ __half g_vthi[Bb * Hh * DKk * Ss];                // (V^T*winv*4096) hi
__device__ __half g_vtlo[Bb * Hh * DKk * Ss];                // lo
__device__ float g_att[Bb * Ss * Gg];

// ---------------- helpers ----------------
__device__ __forceinline__ unsigned smem_u32(const void* p) {
    unsigned a;
    asm("{ .reg .u64 t; cvta.to.shared.u64 t, %1; cvt.u32.u64 %0, t; }" : "=r"(a) : "l"(p));
    return a;
}
__device__ __forceinline__ float ex2f(float x) {
    float r;
    asm("ex2.approx.ftz.f32 %0, %1;" : "=f"(r) : "f"(x));
    return r;
}
__device__ __forceinline__ void ldsm4(unsigned& r0, unsigned& r1, unsigned& r2,
                                      unsigned& r3, unsigned addr) {
    asm volatile("ldmatrix.sync.aligned.m8n8.x4.shared.b16 {%0,%1,%2,%3}, [%4];"
                 : "=r"(r0), "=r"(r1), "=r"(r2), "=r"(r3) : "r"(addr));
}
__device__ __forceinline__ void mma_bf16(float* c, const unsigned* a, const unsigned* b) {
    asm volatile(
        "mma.sync.aligned.m16n8k16.row.col.f32.bf16.bf16.f32 "
        "{%0,%1,%2,%3},{%4,%5,%6,%7},{%8,%9},{%0,%1,%2,%3};"
        : "+f"(c[0]), "+f"(c[1]), "+f"(c[2]), "+f"(c[3])
        : "r"(a[0]), "r"(a[1]), "r"(a[2]), "r"(a[3]), "r"(b[0]), "r"(b[1]));
}
__device__ __forceinline__ void mma_f16(float* c, const unsigned* a, const unsigned* b) {
    asm volatile(
        "mma.sync.aligned.m16n8k16.row.col.f32.f16.f16.f32 "
        "{%0,%1,%2,%3},{%4,%5,%6,%7},{%8,%9},{%0,%1,%2,%3};"
        : "+f"(c[0]), "+f"(c[1]), "+f"(c[2]), "+f"(c[3])
        : "r"(a[0]), "r"(a[1]), "r"(a[2]), "r"(a[3]), "r"(b[0]), "r"(b[1]));
}

// ---------------- fp32 projection GEMM (+ optional bf16 hi/lo split out) ----
template <int SPLIT>
__device__ __forceinline__ void gemm_body(
    const float* __restrict__ A, int lda, const float* __restrict__ W,
    const float* __restrict__ bias, float* __restrict__ C,
    __nv_bfloat16* __restrict__ Chi, __nv_bfloat16* __restrict__ Clo, int K)
{
    __shared__ float As[16][68];
    __shared__ float Ws[16][68];
    const int tid = threadIdx.x, tx = tid & 15, ty = tid >> 4;
    const int m0 = blockIdx.y * 64, n0 = blockIdx.x * 64;
    const int r = tid >> 2, kc = (tid & 3) * 4;
    float acc[4][4] = {};
    for (int k0 = 0; k0 < K; k0 += 16) {
        float4 a4 = *reinterpret_cast<const float4*>(&A[(size_t)(m0 + r) * lda + k0 + kc]);
        As[kc][r] = a4.x; As[kc+1][r] = a4.y; As[kc+2][r] = a4.z; As[kc+3][r] = a4.w;
        float4 w4 = *reinterpret_cast<const float4*>(&W[(size_t)(n0 + r) * K + k0 + kc]);
        Ws[kc][r] = w4.x; Ws[kc+1][r] = w4.y; Ws[kc+2][r] = w4.z; Ws[kc+3][r] = w4.w;
        __syncthreads();
        #pragma unroll
        for (int k = 0; k < 16; k++) {
            float4 av = *reinterpret_cast<const float4*>(&As[k][ty * 4]);
            float4 wv = *reinterpret_cast<const float4*>(&Ws[k][tx * 4]);
            float a[4] = {av.x, av.y, av.z, av.w}, w[4] = {wv.x, wv.y, wv.z, wv.w};
            #pragma unroll
            for (int i = 0; i < 4; i++)
                #pragma unroll
                for (int j = 0; j < 4; j++) acc[i][j] += a[i] * w[j];
        }
        __syncthreads();
    }
    #pragma unroll
    for (int i = 0; i < 4; i++) {
        const int m = m0 + ty * 4 + i, nb = n0 + tx * 4;
        float o[4];
        #pragma unroll
        for (int j = 0; j < 4; j++) o[j] = acc[i][j] + bias[nb + j];
        if (SPLIT) {
            __nv_bfloat162 h01 = __floats2bfloat162_rn(o[0], o[1]);
            __nv_bfloat162 h23 = __floats2bfloat162_rn(o[2], o[3]);
            __nv_bfloat162 l01 = __floats2bfloat162_rn(o[0]-__bfloat162float(h01.x), o[1]-__bfloat162float(h01.y));
            __nv_bfloat162 l23 = __floats2bfloat162_rn(o[2]-__bfloat162float(h23.x), o[3]-__bfloat162float(h23.y));
            uint2 hv, lv;
            hv.x = *(unsigned*)&h01; hv.y = *(unsigned*)&h23;
            lv.x = *(unsigned*)&l01; lv.y = *(unsigned*)&l23;
            *reinterpret_cast<uint2*>(&Chi[(size_t)m * Gg + nb]) = hv;
            *reinterpret_cast<uint2*>(&Clo[(size_t)m * Gg + nb]) = lv;
        } else {
            *reinterpret_cast<float4*>(&C[(size_t)m * Gg + nb]) = make_float4(o[0], o[1], o[2], o[3]);
        }
    }
}
__global__ __launch_bounds__(256) void gemm_f32_kernel(
    const float* __restrict__ A, int lda, const float* __restrict__ W,
    const float* __restrict__ bias, float* __restrict__ C, int K)
{ gemm_body<0>(A, lda, W, bias, C, nullptr, nullptr, K); }

__global__ __launch_bounds__(256) void gemm_split_kernel(
    const float* __restrict__ A, int lda, const float* __restrict__ W,
    const float* __restrict__ bias, __nv_bfloat16* __restrict__ Chi,
    __nv_bfloat16* __restrict__ Clo, int K)
{ gemm_body<1>(A, lda, W, bias, nullptr, Chi, Clo, K); }

// ---------------------------------------------------------------------------
// scores: P(fp16) = exp(scale*QK^T) via mma.sync bf16x3.  CTA 128x128, K=64.
// 8 warps 2(m) x 4(n).  Fused fp32 column sums; P staged in SMEM (reusing
// K region) then fully-coalesced 16B stores.  grid (32,32,8), 256 thr.
// ---------------------------------------------------------------------------
__global__ __launch_bounds__(256) void scores_wm_kernel(
    const __nv_bfloat16* __restrict__ qhi, const __nv_bfloat16* __restrict__ qlo,
    const __nv_bfloat16* __restrict__ khi, const __nv_bfloat16* __restrict__ klo,
    __half* __restrict__ P, float* __restrict__ part)
{
    extern __shared__ char sm[];
    const int QH = 0, QL = 18432, KH = 36864, KL = 55296;
    const int STG_BASE = 36864;
    const int tid = threadIdx.x, lane = tid & 31, wid = tid >> 5;
    const int wm = wid >> 2, wn = wid & 3;
    const int bh = blockIdx.z, b = bh >> 2, h = bh & 3;
    const int i0 = blockIdx.y * 128, j0 = blockIdx.x * 128;

    {
        const int row = tid >> 1, half = tid & 1;
        const size_t qoff = ((size_t)(b * Ss + i0 + row)) * Gg + h * DKk + half * 32;
        const size_t koff = ((size_t)(b * Ss + j0 + row)) * Gg + h * DKk + half * 32;
        const unsigned so = row * 144 + half * 64;
        const uint4* q1 = reinterpret_cast<const uint4*>(qhi + qoff);
        const uint4* q2 = reinterpret_cast<const uint4*>(qlo + qoff);
        const uint4* k1 = reinterpret_cast<const uint4*>(khi + koff);
        const uint4* k2 = reinterpret_cast<const uint4*>(klo + koff);
        #pragma unroll
        for (int u = 0; u < 4; u++) {
            *reinterpret_cast<uint4*>(sm + QH + so + u * 16) = q1[u];
            *reinterpret_cast<uint4*>(sm + QL + so + u * 16) = q2[u];
            *reinterpret_cast<uint4*>(sm + KH + so + u * 16) = k1[u];
            *reinterpret_cast<uint4*>(sm + KL + so + u * 16) = k2[u];
        }
    }
    __syncthreads();

    const unsigned base = smem_u32(sm);
    const int qr = lane >> 2, qc = lane & 3;
    const unsigned aoff = (wm * 64 + (lane & 15)) * 144 + ((lane >> 4) * 8) * 2;
    const unsigned boff = (wn * 32 + ((lane >> 4) & 1) * 8 + (lane & 7)) * 144
                        + (((lane >> 3) & 1) * 8) * 2;

    float acc[4][4][4] = {};
    #pragma unroll
    for (int kk = 0; kk < 4; kk++) {
        unsigned aH[4][4], aL[4][4], bH[2][4], bL[2][4];
        #pragma unroll
        for (int mt = 0; mt < 4; mt++) {
            const unsigned ad = base + QH + aoff + mt * 2304 + kk * 32;
            ldsm4(aH[mt][0], aH[mt][1], aH[mt][2], aH[mt][3], ad);
            ldsm4(aL[mt][0], aL[mt][1], aL[mt][2], aL[mt][3], ad + (QL - QH));
        }
        #pragma unroll
        for (int g = 0; g < 2; g++) {
            const unsigned bd = base + KH + boff + g * 2304 + kk * 32;
            ldsm4(bH[g][0], bH[g][1], bH[g][2], bH[g][3], bd);
            ldsm4(bL[g][0], bL[g][1], bL[g][2], bL[g][3], bd + (KL - KH));
        }
        #pragma unroll
        for (int mt = 0; mt < 4; mt++)
            #pragma unroll
            for (int nt = 0; nt < 4; nt++) {
                const unsigned* pbh = &bH[nt >> 1][(nt & 1) * 2];
                const unsigned* pbl = &bL[nt >> 1][(nt & 1) * 2];
                mma_bf16(acc[mt][nt], aH[mt], pbh);
                mma_bf16(acc[mt][nt], aH[mt], pbl);
                mma_bf16(acc[mt][nt], aL[mt], pbh);
            }
    }

    #pragma unroll
    for (int mt = 0; mt < 4; mt++)
        #pragma unroll
        for (int nt = 0; nt < 4; nt++)
            #pragma unroll
            for (int r = 0; r < 4; r++)
                acc[mt][nt][r] = ex2f(acc[mt][nt][r] * EXP2K);

    // deterministic fp32 column partial sums over this warp's 64 rows
    const int jbase = j0 + wn * 32;
    #pragma unroll
    for (int nt = 0; nt < 4; nt++) {
        #pragma unroll
        for (int p = 0; p < 2; p++) {
            float s = 0.f;
            #pragma unroll
            for (int mt = 0; mt < 4; mt++) s += acc[mt][nt][p] + acc[mt][nt][p + 2];
            #pragma unroll
            for (int o = 4; o < 32; o <<= 1) s += __shfl_xor_sync(0xffffffffu, s, o);
            if (qr == 0)
                part[((size_t)(bh * 32 + blockIdx.y) * 2 + wm) * Ss
                     + jbase + nt * 8 + qc * 2 + p] = s;
        }
    }

    // stage fp16 P tile in SMEM (stride 136 elems), then coalesced 16B stores
    __syncthreads();
    __half* stg = reinterpret_cast<__half*>(sm + STG_BASE);
    #pragma unroll
    for (int mt = 0; mt < 4; mt++) {
        const int r0 = wm * 64 + mt * 16 + qr;
        #pragma unroll
        for (int nt = 0; nt < 4; nt++) {
            const int col = wn * 32 + nt * 8 + qc * 2;
            #pragma unroll
            for (int pr = 0; pr < 2; pr++) {
                __half2 h2 = __floats2half2_rn(acc[mt][nt][pr * 2],
                                               acc[mt][nt][pr * 2 + 1]);
                *reinterpret_cast<__half2*>(stg + (r0 + pr * 8) * 136 + col) = h2;
            }
        }
    }
    __syncthreads();
    {
        const size_t pb = ((size_t)bh * Ss + i0) * Ss + j0;
        #pragma unroll
        for (int ps = 0; ps < 8; ps++) {
            const int el = ps * 2048 + tid * 8;
            const int row = el >> 7, col = el & 127;
            uint4 vv = *reinterpret_cast<const uint4*>(stg + row * 136 + col);
            *reinterpret_cast<uint4*>(P + pb + (size_t)row * Ss + col) = vv;
        }
    }
}

// winv[bh,j] = 1/sum_{c<64} part[bh*64+c, j].  grid (16,8) x 256
__global__ __launch_bounds__(256) void colsum_final_kernel(
    const float* __restrict__ part, float* __restrict__ winv)
{
    const int j = blockIdx.x * 256 + threadIdx.x;
    const int bh = blockIdx.y;
    const float* p = part + (size_t)bh * 64 * Ss + j;
    float s = 0.f;
    #pragma unroll 8
    for (int c = 0; c < 64; c++) s += p[(size_t)c * Ss];
    winv[(size_t)bh * Ss + j] = 1.0f / s;
}

// vT[bh,d,j] = v[b,j,h*64+d]*winv[bh,j]*4096 -> fp16 hi/lo.  grid (64,8) x 256
__global__ __launch_bounds__(256) void scale_v_t_kernel(
    const float* __restrict__ v, const float* __restrict__ winv,
    __half* __restrict__ tH, __half* __restrict__ tL)
{
    __shared__ float ts[64][65];
    const int tid = threadIdx.x, bh = blockIdx.y, b = bh >> 2, h = bh & 3;
    const int j0 = blockIdx.x * 64;
    {
        const int j = tid >> 2, c0 = (tid & 3) * 16;
        const float* src = v + ((size_t)(b * Ss + j0 + j)) * Gg + h * DKk + c0;
        #pragma unroll
        for (int u = 0; u < 4; u++) {
            float4 f = *reinterpret_cast<const float4*>(src + u * 4);
            ts[j][c0 + 4*u]     = f.x; ts[j][c0 + 4*u + 1] = f.y;
            ts[j][c0 + 4*u + 2] = f.z; ts[j][c0 + 4*u + 3] = f.w;
        }
    }
    __syncthreads();
    const int d = tid >> 2, jj0 = (tid & 3) * 16;
    const size_t ob = (((size_t)bh) * DKk + d) * Ss + j0 + jj0;
    const float* wv = winv + (size_t)bh * Ss + j0 + jj0;
    __half hbuf[16], lbuf[16];
    #pragma unroll
    for (int u = 0; u < 16; u++) {
        float f = ts[jj0 + u][d] * wv[u] * VSCALE;
        __half hb = __float2half_rn(f);
        hbuf[u] = hb;
        lbuf[u] = __float2half_rn(f - __half2float(hb));
    }
    #pragma unroll
    for (int u = 0; u < 2; u++) {
        *reinterpret_cast<uint4*>(tH + ob + u * 8) = reinterpret_cast<uint4*>(hbuf)[u];
        *reinterpret_cast<uint4*>(tL + ob + u * 8) = reinterpret_cast<uint4*>(lbuf)[u];
    }
}

// ---------------------------------------------------------------------------
// pv: Att = (P @ Vw^T)/4096, fp16 MMA, 2 passes (Vhi, Vlo).  CTA 128x64,
// K=4096 (64 chunks).  8 warps 4(m) x 2(n).  grid (32,8), 256 thr.
// dyn smem = 128*144 + 2*64*144 = 36864 B.  Register-prefetch pipeline.
// ---------------------------------------------------------------------------
__global__ __launch_bounds__(256) void pv_wm_kernel(
    const __half* __restrict__ P, const __half* __restrict__ vthi,
    const __half* __restrict__ vtlo, float* __restrict__ att)
{
    extern __shared__ char sm[];
    const int PH = 0, VH = 18432, VL = 27648;
    const int tid = threadIdx.x, lane = tid & 31, wid = tid >> 5;
    const int wm = wid >> 1, wn = wid & 1;
    const int bh = blockIdx.y, b = bh >> 2, h = bh & 3;
    const int i0 = blockIdx.x * 128;
    const int qr = lane >> 2, qc = lane & 3;

    const int prow = tid >> 1, phalf = tid & 1;
    const __half* pS = P + ((size_t)bh * Ss + i0 + prow) * Ss + phalf * 32;
    const unsigned pso = prow * 144 + phalf * 64;
    // V: thread -> tile (hi/lo), row d, half
    const int vtile = tid >> 7, vrow = (tid >> 1) & 63, vhalf = tid & 1;
    const __half* vS = (vtile ? vtlo : vthi)
                     + ((size_t)bh * DKk + vrow) * Ss + vhalf * 32;
    const unsigned vso = (vtile ? VL : VH) + vrow * 144 + vhalf * 64;

    const unsigned base = smem_u32(sm);
    const unsigned aoff = (wm * 32 + (lane & 15)) * 144 + ((lane >> 4) * 8) * 2;
    const unsigned boff = (wn * 32 + ((lane >> 4) & 1) * 8 + (lane & 7)) * 144
                        + (((lane >> 3) & 1) * 8) * 2;

    float acc[2][4][4] = {};
    uint4 rp[4], rv[4];

    #pragma unroll
    for (int u = 0; u < 4; u++) {
        rp[u] = reinterpret_cast<const uint4*>(pS)[u];
        rv[u] = reinterpret_cast<const uint4*>(vS)[u];
    }

    for (int c = 0; c < 64; c++) {
        #pragma unroll
        for (int u = 0; u < 4; u++) {
            *reinterpret_cast<uint4*>(sm + PH + pso + u * 16) = rp[u];
            *reinterpret_cast<uint4*>(sm + vso + u * 16)      = rv[u];
        }
        __syncthreads();

        if (c < 63) {
            const size_t go = (size_t)(c + 1) * 64;
            #pragma unroll
            for (int u = 0; u < 4; u++) {
                rp[u] = reinterpret_cast<const uint4*>(pS + go)[u];
                rv[u] = reinterpret_cast<const uint4*>(vS + go)[u];
            }
        }

        #pragma unroll
        for (int kk = 0; kk < 4; kk++) {
            unsigned aH[2][4], bH[2][4], bL[2][4];
            #pragma unroll
            for (int mt = 0; mt < 2; mt++) {
                const unsigned ad = base + PH + aoff + mt * 2304 + kk * 32;
                ldsm4(aH[mt][0], aH[mt][1], aH[mt][2], aH[mt][3], ad);
            }
            #pragma unroll
            for (int g = 0; g < 2; g++) {
                const unsigned bd = base + VH + boff + g * 2304 + kk * 32;
                ldsm4(bH[g][0], bH[g][1], bH[g][2], bH[g][3], bd);
                ldsm4(bL[g][0], bL[g][1], bL[g][2], bL[g][3], bd + (VL - VH));
            }
            #pragma unroll
            for (int mt = 0; mt < 2; mt++)
                #pragma unroll
                for (int nt = 0; nt < 4; nt++) {
                    mma_f16(acc[mt][nt], aH[mt], &bH[nt >> 1][(nt & 1) * 2]);
                    mma_f16(acc[mt][nt], aH[mt], &bL[nt >> 1][(nt & 1) * 2]);
                }
        }
        __syncthreads();
    }

    #pragma unroll
    for (int mt = 0; mt < 2; mt++) {
        const int row0 = i0 + wm * 32 + mt * 16 + qr;
        #pragma unroll
        for (int nt = 0; nt < 4; nt++) {
            const int col = h * DKk + wn * 32 + nt * 8 + qc * 2;
            #pragma unroll
            for (int pr = 0; pr < 2; pr++) {
                float2 o = make_float2(acc[mt][nt][pr * 2] * OSCALE,
                                       acc[mt][nt][pr * 2 + 1] * OSCALE);
                *reinterpret_cast<float2*>(
                    att + ((size_t)(b * Ss + row0 + pr * 8)) * Gg + col) = o;
            }
        }
    }
}

// ---------------------------------------------------------------------------
extern "C" void kernel_launch(void* const* d_in, const int* in_sizes, int n_in,
                              void* d_out, int out_size)
{
    const float* x  = (const float*)d_in[0];
    const float* wq = (const float*)d_in[1];
    const float* bq = (const float*)d_in[2];
    const float* wk = (const float*)d_in[3];
    const float* bk = (const float*)d_in[4];
    const float* wv = (const float*)d_in[5];
    const float* bv = (const float*)d_in[6];
    const float* wo = (const float*)d_in[7];
    const float* bo = (const float*)d_in[8];
    float* out = (float*)d_out;

    __nv_bfloat16 *qhi, *qlo, *khi, *klo;
    __half *p, *vthi, *vtlo;
    float *v, *part, *winv, *att;
    cudaGetSymbolAddress((void**)&qhi, g_qhi);  cudaGetSymbolAddress((void**)&qlo, g_qlo);
    cudaGetSymbolAddress((void**)&khi, g_khi);  cudaGetSymbolAddress((void**)&klo, g_klo);
    cudaGetSymbolAddress((void**)&v,   g_v);
    cudaGetSymbolAddress((void**)&p,   g_p);
    cudaGetSymbolAddress((void**)&part,g_part); cudaGetSymbolAddress((void**)&winv,g_winv);
    cudaGetSymbolAddress((void**)&vthi,g_vthi); cudaGetSymbolAddress((void**)&vtlo,g_vtlo);
    cudaGetSymbolAddress((void**)&att, g_att);

    const int SC_SMEM = 73728;
    const int PV_SMEM = 36864;
    cudaFuncSetAttribute(scores_wm_kernel, cudaFuncAttributeMaxDynamicSharedMemorySize, SC_SMEM);
    cudaFuncSetAttribute(pv_wm_kernel,     cudaFuncAttributeMaxDynamicSharedMemorySize, PV_SMEM);

    dim3 gProj(4, 128);
    gemm_split_kernel<<<gProj, 256>>>(x,          DIMd, wq, bq, qhi, qlo, Gg);
    gemm_split_kernel<<<gProj, 256>>>(x + Gg,     DIMd, wk, bk, khi, klo, Gg);
    gemm_f32_kernel  <<<gProj, 256>>>(x + 2 * Gg, DIMd, wv, bv, v, Gg);

    scores_wm_kernel<<<dim3(32, 32, 8), 256, SC_SMEM>>>(qhi, qlo, khi, klo, p, part);
    colsum_final_kernel<<<dim3(16, 8), 256>>>(part, winv);
    scale_v_t_kernel<<<dim3(64, 8), 256>>>(v, winv, vthi, vtlo);
    pv_wm_kernel<<<dim3(32, 8), 256, PV_SMEM>>>(p, vthi, vtlo, att);

    gemm_f32_kernel<<<gProj, 256>>>(att, Gg, wo, bo, out, Gg);
}

// round 7
// speedup vs baseline: 2.7342x; 1.1704x over previous
#include <cuda_runtime.h>
#include <cuda_bf16.h>
#include <cuda_fp16.h>
#include <math.h>

#define Bb   2
#define Ss   4096
#define Gg   256
#define Hh   4
#define DKk  64
#define DIMd 768
#define EXP2K (0.125f * 1.44269504088896341f)
#define VSCALE 4096.0f
#define OSCALE (1.0f / 4096.0f)
#define NSG (Bb * Ss * Gg)

// ---------------- scratch ----------------
__device__ __nv_bfloat16 g_xh[3 * NSG];      // x slices hi (q,k,v inputs)
__device__ __nv_bfloat16 g_xl[3 * NSG];
__device__ __nv_bfloat16 g_wh[4 * Gg * Gg];  // wq,wk,wv,wo hi
__device__ __nv_bfloat16 g_wl[4 * Gg * Gg];
__device__ __nv_bfloat16 g_qhi[NSG];
__device__ __nv_bfloat16 g_qlo[NSG];
__device__ __nv_bfloat16 g_khi[NSG];
__device__ __nv_bfloat16 g_klo[NSG];
__device__ float         g_v  [NSG];
__device__ __half g_p[(size_t)Bb * Hh * Ss * Ss];            // 268 MB, fp16
__device__ float g_part[(size_t)Bb * Hh * 64 * Ss];
__device__ float g_winv[Bb * Hh * Ss];
__device__ __half g_vthi[Bb * Hh * DKk * Ss];
__device__ __half g_vtlo[Bb * Hh * DKk * Ss];
__device__ float g_att[NSG];
__device__ __nv_bfloat16 g_atth[NSG];
__device__ __nv_bfloat16 g_attl[NSG];

// ---------------- helpers ----------------
__device__ __forceinline__ unsigned smem_u32(const void* p) {
    unsigned a;
    asm("{ .reg .u64 t; cvta.to.shared.u64 t, %1; cvt.u32.u64 %0, t; }" : "=r"(a) : "l"(p));
    return a;
}
__device__ __forceinline__ float ex2f(float x) {
    float r;
    asm("ex2.approx.ftz.f32 %0, %1;" : "=f"(r) : "f"(x));
    return r;
}
__device__ __forceinline__ void ldsm4(unsigned& r0, unsigned& r1, unsigned& r2,
                                      unsigned& r3, unsigned addr) {
    asm volatile("ldmatrix.sync.aligned.m8n8.x4.shared.b16 {%0,%1,%2,%3}, [%4];"
                 : "=r"(r0), "=r"(r1), "=r"(r2), "=r"(r3) : "r"(addr));
}
__device__ __forceinline__ void mma_bf16(float* c, const unsigned* a, const unsigned* b) {
    asm volatile(
        "mma.sync.aligned.m16n8k16.row.col.f32.bf16.bf16.f32 "
        "{%0,%1,%2,%3},{%4,%5,%6,%7},{%8,%9},{%0,%1,%2,%3};"
        : "+f"(c[0]), "+f"(c[1]), "+f"(c[2]), "+f"(c[3])
        : "r"(a[0]), "r"(a[1]), "r"(a[2]), "r"(a[3]), "r"(b[0]), "r"(b[1]));
}
__device__ __forceinline__ void mma_f16(float* c, const unsigned* a, const unsigned* b) {
    asm volatile(
        "mma.sync.aligned.m16n8k16.row.col.f32.f16.f16.f32 "
        "{%0,%1,%2,%3},{%4,%5,%6,%7},{%8,%9},{%0,%1,%2,%3};"
        : "+f"(c[0]), "+f"(c[1]), "+f"(c[2]), "+f"(c[3])
        : "r"(a[0]), "r"(a[1]), "r"(a[2]), "r"(a[3]), "r"(b[0]), "r"(b[1]));
}
__device__ __forceinline__ void split2(float a, float b, unsigned& h, unsigned& l) {
    __nv_bfloat162 h2 = __floats2bfloat162_rn(a, b);
    __nv_bfloat162 l2 = __floats2bfloat162_rn(a - __bfloat162float(h2.x),
                                              b - __bfloat162float(h2.y));
    h = *reinterpret_cast<unsigned*>(&h2);
    l = *reinterpret_cast<unsigned*>(&l2);
}

// ---------------- split kernels ----------------
// x[B*S,768] -> 3 slices bf16 hi/lo. grid 6144 x 256 (float4 per thread).
__global__ __launch_bounds__(256) void split_x_kernel(
    const float* __restrict__ x, __nv_bfloat16* __restrict__ hi,
    __nv_bfloat16* __restrict__ lo)
{
    const int i = blockIdx.x * 256 + threadIdx.x;
    float4 f = reinterpret_cast<const float4*>(x)[i];
    const int row = i / 192, c4 = i - row * 192;
    const int slice = c4 >> 6, w4 = c4 & 63;
    const size_t o = (size_t)slice * NSG + (size_t)row * Gg + w4 * 4;
    uint2 hv, lv;
    split2(f.x, f.y, hv.x, lv.x);
    split2(f.z, f.w, hv.y, lv.y);
    *reinterpret_cast<uint2*>(hi + o) = hv;
    *reinterpret_cast<uint2*>(lo + o) = lv;
}

// generic fp32 -> bf16 hi/lo split (n multiple of 4)
__global__ __launch_bounds__(256) void split1_kernel(
    const float* __restrict__ src, __nv_bfloat16* __restrict__ hi,
    __nv_bfloat16* __restrict__ lo, int n4)
{
    const int i = blockIdx.x * 256 + threadIdx.x;
    if (i >= n4) return;
    float4 f = reinterpret_cast<const float4*>(src)[i];
    uint2 hv, lv;
    split2(f.x, f.y, hv.x, lv.x);
    split2(f.z, f.w, hv.y, lv.y);
    *reinterpret_cast<uint2*>(hi + (size_t)i * 4) = hv;
    *reinterpret_cast<uint2*>(lo + (size_t)i * 4) = lv;
}

// ---------------------------------------------------------------------------
// Tensor-core projection GEMM (bf16x3): C[M,256] = A[M,256] @ W[256,256]^T + b
// CTA 128x64, K=256 in 4 chunks of 64.  8 warps 4(m) x 2(n), warp 32x32.
// SPLIT=1: emit bf16 hi/lo; SPLIT=0: emit fp32.  grid (4, M/128), 256 thr.
// dyn smem 55552 B.
// ---------------------------------------------------------------------------
template <int SPLIT>
__global__ __launch_bounds__(256) void gemm_tc_kernel(
    const __nv_bfloat16* __restrict__ Ahi, const __nv_bfloat16* __restrict__ Alo,
    const __nv_bfloat16* __restrict__ Whi, const __nv_bfloat16* __restrict__ Wlo,
    const float* __restrict__ bias, float* __restrict__ C,
    __nv_bfloat16* __restrict__ Chi, __nv_bfloat16* __restrict__ Clo)
{
    extern __shared__ char sm[];
    const int AH = 0, AL = 18432, WH = 36864, WL = 46080, SBIAS = 55296;
    const int tid = threadIdx.x, lane = tid & 31, wid = tid >> 5;
    const int wm = wid >> 1, wn = wid & 1;
    const int n0 = blockIdx.x * 64, m0 = blockIdx.y * 128;
    const int qr = lane >> 2, qc = lane & 3;

    if (tid < 16)
        *reinterpret_cast<float4*>(sm + SBIAS + tid * 16) =
            *reinterpret_cast<const float4*>(bias + n0 + tid * 4);

    // gmem source pointers (per-thread)
    const int arow = tid >> 1, ahalf = tid & 1;
    const __nv_bfloat16* aH = Ahi + (size_t)(m0 + arow) * Gg + ahalf * 32;
    const __nv_bfloat16* aL = Alo + (size_t)(m0 + arow) * Gg + ahalf * 32;
    const unsigned aso = arow * 144 + ahalf * 64;
    const int wrow = tid >> 2, wq = tid & 3;
    const __nv_bfloat16* wH = Whi + (size_t)(n0 + wrow) * Gg + wq * 16;
    const __nv_bfloat16* wL = Wlo + (size_t)(n0 + wrow) * Gg + wq * 16;
    const unsigned wso = wrow * 144 + wq * 32;

    const unsigned base = smem_u32(sm);
    const unsigned aoff = (wm * 32 + (lane & 15)) * 144 + ((lane >> 4) * 8) * 2;
    const unsigned boff = (wn * 32 + ((lane >> 4) & 1) * 8 + (lane & 7)) * 144
                        + (((lane >> 3) & 1) * 8) * 2;

    float acc[2][4][4] = {};
    uint4 rah[4], ral[4], rwh[2], rwl[2];

    #pragma unroll
    for (int u = 0; u < 4; u++) {
        rah[u] = reinterpret_cast<const uint4*>(aH)[u];
        ral[u] = reinterpret_cast<const uint4*>(aL)[u];
    }
    #pragma unroll
    for (int u = 0; u < 2; u++) {
        rwh[u] = reinterpret_cast<const uint4*>(wH)[u];
        rwl[u] = reinterpret_cast<const uint4*>(wL)[u];
    }

    for (int c = 0; c < 4; c++) {
        #pragma unroll
        for (int u = 0; u < 4; u++) {
            *reinterpret_cast<uint4*>(sm + AH + aso + u * 16) = rah[u];
            *reinterpret_cast<uint4*>(sm + AL + aso + u * 16) = ral[u];
        }
        #pragma unroll
        for (int u = 0; u < 2; u++) {
            *reinterpret_cast<uint4*>(sm + WH + wso + u * 16) = rwh[u];
            *reinterpret_cast<uint4*>(sm + WL + wso + u * 16) = rwl[u];
        }
        __syncthreads();

        if (c < 3) {
            const int go = (c + 1) * 64;
            #pragma unroll
            for (int u = 0; u < 4; u++) {
                rah[u] = reinterpret_cast<const uint4*>(aH + go)[u];
                ral[u] = reinterpret_cast<const uint4*>(aL + go)[u];
            }
            #pragma unroll
            for (int u = 0; u < 2; u++) {
                rwh[u] = reinterpret_cast<const uint4*>(wH + go)[u];
                rwl[u] = reinterpret_cast<const uint4*>(wL + go)[u];
            }
        }

        #pragma unroll
        for (int kk = 0; kk < 4; kk++) {
            unsigned fah[2][4], fal[2][4], fbh[2][4], fbl[2][4];
            #pragma unroll
            for (int mt = 0; mt < 2; mt++) {
                const unsigned ad = base + AH + aoff + mt * 2304 + kk * 32;
                ldsm4(fah[mt][0], fah[mt][1], fah[mt][2], fah[mt][3], ad);
                ldsm4(fal[mt][0], fal[mt][1], fal[mt][2], fal[mt][3], ad + (AL - AH));
            }
            #pragma unroll
            for (int g = 0; g < 2; g++) {
                const unsigned bd = base + WH + boff + g * 2304 + kk * 32;
                ldsm4(fbh[g][0], fbh[g][1], fbh[g][2], fbh[g][3], bd);
                ldsm4(fbl[g][0], fbl[g][1], fbl[g][2], fbl[g][3], bd + (WL - WH));
            }
            #pragma unroll
            for (int mt = 0; mt < 2; mt++)
                #pragma unroll
                for (int nt = 0; nt < 4; nt++) {
                    const unsigned* pbh = &fbh[nt >> 1][(nt & 1) * 2];
                    const unsigned* pbl = &fbl[nt >> 1][(nt & 1) * 2];
                    mma_bf16(acc[mt][nt], fah[mt], pbh);
                    mma_bf16(acc[mt][nt], fah[mt], pbl);
                    mma_bf16(acc[mt][nt], fal[mt], pbh);
                }
        }
        __syncthreads();
    }

    const float* bs = reinterpret_cast<const float*>(sm + SBIAS);
    if (SPLIT) {
        __nv_bfloat16* sh = reinterpret_cast<__nv_bfloat16*>(sm);           // stride 72
        __nv_bfloat16* sl = reinterpret_cast<__nv_bfloat16*>(sm + 18432);
        #pragma unroll
        for (int mt = 0; mt < 2; mt++) {
            const int r0 = wm * 32 + mt * 16 + qr;
            #pragma unroll
            for (int nt = 0; nt < 4; nt++) {
                const int col = wn * 32 + nt * 8 + qc * 2;
                #pragma unroll
                for (int pr = 0; pr < 2; pr++) {
                    const float o0 = acc[mt][nt][pr * 2]     + bs[col];
                    const float o1 = acc[mt][nt][pr * 2 + 1] + bs[col + 1];
                    unsigned hv, lv;
                    split2(o0, o1, hv, lv);
                    *reinterpret_cast<unsigned*>(sh + (r0 + pr * 8) * 72 + col) = hv;
                    *reinterpret_cast<unsigned*>(sl + (r0 + pr * 8) * 72 + col) = lv;
                }
            }
        }
        __syncthreads();
        #pragma unroll
        for (int ps = 0; ps < 4; ps++) {
            const int idx = ps * 2048 + tid * 8;
            const int row = idx >> 6, col = idx & 63;
            uint4 hv = *reinterpret_cast<const uint4*>(sh + row * 72 + col);
            uint4 lv = *reinterpret_cast<const uint4*>(sl + row * 72 + col);
            const size_t o = (size_t)(m0 + row) * Gg + n0 + col;
            *reinterpret_cast<uint4*>(Chi + o) = hv;
            *reinterpret_cast<uint4*>(Clo + o) = lv;
        }
    } else {
        float* sc = reinterpret_cast<float*>(sm);                            // stride 68
        #pragma unroll
        for (int mt = 0; mt < 2; mt++) {
            const int r0 = wm * 32 + mt * 16 + qr;
            #pragma unroll
            for (int nt = 0; nt < 4; nt++) {
                const int col = wn * 32 + nt * 8 + qc * 2;
                #pragma unroll
                for (int pr = 0; pr < 2; pr++) {
                    float2 o = make_float2(acc[mt][nt][pr * 2]     + bs[col],
                                           acc[mt][nt][pr * 2 + 1] + bs[col + 1]);
                    *reinterpret_cast<float2*>(sc + (r0 + pr * 8) * 68 + col) = o;
                }
            }
        }
        __syncthreads();
        #pragma unroll
        for (int ps = 0; ps < 8; ps++) {
            const int idx = ps * 1024 + tid * 4;
            const int row = idx >> 6, col = idx & 63;
            float4 v = *reinterpret_cast<const float4*>(sc + row * 68 + col);
            *reinterpret_cast<float4*>(C + (size_t)(m0 + row) * Gg + n0 + col) = v;
        }
    }
}

// ---------------------------------------------------------------------------
// scores: P(fp16) = exp(scale*QK^T) via mma.sync bf16x3.  (unchanged from R6)
// ---------------------------------------------------------------------------
__global__ __launch_bounds__(256) void scores_wm_kernel(
    const __nv_bfloat16* __restrict__ qhi, const __nv_bfloat16* __restrict__ qlo,
    const __nv_bfloat16* __restrict__ khi, const __nv_bfloat16* __restrict__ klo,
    __half* __restrict__ P, float* __restrict__ part)
{
    extern __shared__ char sm[];
    const int QH = 0, QL = 18432, KH = 36864, KL = 55296;
    const int STG_BASE = 36864;
    const int tid = threadIdx.x, lane = tid & 31, wid = tid >> 5;
    const int wm = wid >> 2, wn = wid & 3;
    const int bh = blockIdx.z, b = bh >> 2, h = bh & 3;
    const int i0 = blockIdx.y * 128, j0 = blockIdx.x * 128;

    {
        const int row = tid >> 1, half = tid & 1;
        const size_t qoff = ((size_t)(b * Ss + i0 + row)) * Gg + h * DKk + half * 32;
        const size_t koff = ((size_t)(b * Ss + j0 + row)) * Gg + h * DKk + half * 32;
        const unsigned so = row * 144 + half * 64;
        const uint4* q1 = reinterpret_cast<const uint4*>(qhi + qoff);
        const uint4* q2 = reinterpret_cast<const uint4*>(qlo + qoff);
        const uint4* k1 = reinterpret_cast<const uint4*>(khi + koff);
        const uint4* k2 = reinterpret_cast<const uint4*>(klo + koff);
        #pragma unroll
        for (int u = 0; u < 4; u++) {
            *reinterpret_cast<uint4*>(sm + QH + so + u * 16) = q1[u];
            *reinterpret_cast<uint4*>(sm + QL + so + u * 16) = q2[u];
            *reinterpret_cast<uint4*>(sm + KH + so + u * 16) = k1[u];
            *reinterpret_cast<uint4*>(sm + KL + so + u * 16) = k2[u];
        }
    }
    __syncthreads();

    const unsigned base = smem_u32(sm);
    const int qr = lane >> 2, qc = lane & 3;
    const unsigned aoff = (wm * 64 + (lane & 15)) * 144 + ((lane >> 4) * 8) * 2;
    const unsigned boff = (wn * 32 + ((lane >> 4) & 1) * 8 + (lane & 7)) * 144
                        + (((lane >> 3) & 1) * 8) * 2;

    float acc[4][4][4] = {};
    #pragma unroll
    for (int kk = 0; kk < 4; kk++) {
        unsigned aH[4][4], aL[4][4], bH[2][4], bL[2][4];
        #pragma unroll
        for (int mt = 0; mt < 4; mt++) {
            const unsigned ad = base + QH + aoff + mt * 2304 + kk * 32;
            ldsm4(aH[mt][0], aH[mt][1], aH[mt][2], aH[mt][3], ad);
            ldsm4(aL[mt][0], aL[mt][1], aL[mt][2], aL[mt][3], ad + (QL - QH));
        }
        #pragma unroll
        for (int g = 0; g < 2; g++) {
            const unsigned bd = base + KH + boff + g * 2304 + kk * 32;
            ldsm4(bH[g][0], bH[g][1], bH[g][2], bH[g][3], bd);
            ldsm4(bL[g][0], bL[g][1], bL[g][2], bL[g][3], bd + (KL - KH));
        }
        #pragma unroll
        for (int mt = 0; mt < 4; mt++)
            #pragma unroll
            for (int nt = 0; nt < 4; nt++) {
                const unsigned* pbh = &bH[nt >> 1][(nt & 1) * 2];
                const unsigned* pbl = &bL[nt >> 1][(nt & 1) * 2];
                mma_bf16(acc[mt][nt], aH[mt], pbh);
                mma_bf16(acc[mt][nt], aH[mt], pbl);
                mma_bf16(acc[mt][nt], aL[mt], pbh);
            }
    }

    #pragma unroll
    for (int mt = 0; mt < 4; mt++)
        #pragma unroll
        for (int nt = 0; nt < 4; nt++)
            #pragma unroll
            for (int r = 0; r < 4; r++)
                acc[mt][nt][r] = ex2f(acc[mt][nt][r] * EXP2K);

    const int jbase = j0 + wn * 32;
    #pragma unroll
    for (int nt = 0; nt < 4; nt++) {
        #pragma unroll
        for (int p = 0; p < 2; p++) {
            float s = 0.f;
            #pragma unroll
            for (int mt = 0; mt < 4; mt++) s += acc[mt][nt][p] + acc[mt][nt][p + 2];
            #pragma unroll
            for (int o = 4; o < 32; o <<= 1) s += __shfl_xor_sync(0xffffffffu, s, o);
            if (qr == 0)
                part[((size_t)(bh * 32 + blockIdx.y) * 2 + wm) * Ss
                     + jbase + nt * 8 + qc * 2 + p] = s;
        }
    }

    __syncthreads();
    __half* stg = reinterpret_cast<__half*>(sm + STG_BASE);
    #pragma unroll
    for (int mt = 0; mt < 4; mt++) {
        const int r0 = wm * 64 + mt * 16 + qr;
        #pragma unroll
        for (int nt = 0; nt < 4; nt++) {
            const int col = wn * 32 + nt * 8 + qc * 2;
            #pragma unroll
            for (int pr = 0; pr < 2; pr++) {
                __half2 h2 = __floats2half2_rn(acc[mt][nt][pr * 2],
                                               acc[mt][nt][pr * 2 + 1]);
                *reinterpret_cast<__half2*>(stg + (r0 + pr * 8) * 136 + col) = h2;
            }
        }
    }
    __syncthreads();
    {
        const size_t pb = ((size_t)bh * Ss + i0) * Ss + j0;
        #pragma unroll
        for (int ps = 0; ps < 8; ps++) {
            const int el = ps * 2048 + tid * 8;
            const int row = el >> 7, col = el & 127;
            uint4 vv = *reinterpret_cast<const uint4*>(stg + row * 136 + col);
            *reinterpret_cast<uint4*>(P + pb + (size_t)row * Ss + col) = vv;
        }
    }
}

// winv[bh,j] = 1/sum_{c<64} part[bh*64+c, j].  grid (16,8) x 256
__global__ __launch_bounds__(256) void colsum_final_kernel(
    const float* __restrict__ part, float* __restrict__ winv)
{
    const int j = blockIdx.x * 256 + threadIdx.x;
    const int bh = blockIdx.y;
    const float* p = part + (size_t)bh * 64 * Ss + j;
    float s = 0.f;
    #pragma unroll 8
    for (int c = 0; c < 64; c++) s += p[(size_t)c * Ss];
    winv[(size_t)bh * Ss + j] = 1.0f / s;
}

// vT[bh,d,j] = v[b,j,h*64+d]*winv[bh,j]*4096 -> fp16 hi/lo.  grid (64,8) x 256
__global__ __launch_bounds__(256) void scale_v_t_kernel(
    const float* __restrict__ v, const float* __restrict__ winv,
    __half* __restrict__ tH, __half* __restrict__ tL)
{
    __shared__ float ts[64][65];
    const int tid = threadIdx.x, bh = blockIdx.y, b = bh >> 2, h = bh & 3;
    const int j0 = blockIdx.x * 64;
    {
        const int j = tid >> 2, c0 = (tid & 3) * 16;
        const float* src = v + ((size_t)(b * Ss + j0 + j)) * Gg + h * DKk + c0;
        #pragma unroll
        for (int u = 0; u < 4; u++) {
            float4 f = *reinterpret_cast<const float4*>(src + u * 4);
            ts[j][c0 + 4*u]     = f.x; ts[j][c0 + 4*u + 1] = f.y;
            ts[j][c0 + 4*u + 2] = f.z; ts[j][c0 + 4*u + 3] = f.w;
        }
    }
    __syncthreads();
    const int d = tid >> 2, jj0 = (tid & 3) * 16;
    const size_t ob = (((size_t)bh) * DKk + d) * Ss + j0 + jj0;
    const float* wv = winv + (size_t)bh * Ss + j0 + jj0;
    __half hbuf[16], lbuf[16];
    #pragma unroll
    for (int u = 0; u < 16; u++) {
        float f = ts[jj0 + u][d] * wv[u] * VSCALE;
        __half hb = __float2half_rn(f);
        hbuf[u] = hb;
        lbuf[u] = __float2half_rn(f - __half2float(hb));
    }
    #pragma unroll
    for (int u = 0; u < 2; u++) {
        *reinterpret_cast<uint4*>(tH + ob + u * 8) = reinterpret_cast<uint4*>(hbuf)[u];
        *reinterpret_cast<uint4*>(tL + ob + u * 8) = reinterpret_cast<uint4*>(lbuf)[u];
    }
}

// ---------------------------------------------------------------------------
// pv: Att = (P @ Vw^T)/4096, fp16 MMA, 2 passes (Vhi, Vlo).  (unchanged R6)
// ---------------------------------------------------------------------------
__global__ __launch_bounds__(256) void pv_wm_kernel(
    const __half* __restrict__ P, const __half* __restrict__ vthi,
    const __half* __restrict__ vtlo, float* __restrict__ att)
{
    extern __shared__ char sm[];
    const int PH = 0, VH = 18432, VL = 27648;
    const int tid = threadIdx.x, lane = tid & 31, wid = tid >> 5;
    const int wm = wid >> 1, wn = wid & 1;
    const int bh = blockIdx.y, b = bh >> 2, h = bh & 3;
    const int i0 = blockIdx.x * 128;
    const int qr = lane >> 2, qc = lane & 3;

    const int prow = tid >> 1, phalf = tid & 1;
    const __half* pS = P + ((size_t)bh * Ss + i0 + prow) * Ss + phalf * 32;
    const unsigned pso = prow * 144 + phalf * 64;
    const int vtile = tid >> 7, vrow = (tid >> 1) & 63, vhalf = tid & 1;
    const __half* vS = (vtile ? vtlo : vthi)
                     + ((size_t)bh * DKk + vrow) * Ss + vhalf * 32;
    const unsigned vso = (vtile ? VL : VH) + vrow * 144 + vhalf * 64;

    const unsigned base = smem_u32(sm);
    const unsigned aoff = (wm * 32 + (lane & 15)) * 144 + ((lane >> 4) * 8) * 2;
    const unsigned boff = (wn * 32 + ((lane >> 4) & 1) * 8 + (lane & 7)) * 144
                        + (((lane >> 3) & 1) * 8) * 2;

    float acc[2][4][4] = {};
    uint4 rp[4], rv[4];

    #pragma unroll
    for (int u = 0; u < 4; u++) {
        rp[u] = reinterpret_cast<const uint4*>(pS)[u];
        rv[u] = reinterpret_cast<const uint4*>(vS)[u];
    }

    for (int c = 0; c < 64; c++) {
        #pragma unroll
        for (int u = 0; u < 4; u++) {
            *reinterpret_cast<uint4*>(sm + PH + pso + u * 16) = rp[u];
            *reinterpret_cast<uint4*>(sm + vso + u * 16)      = rv[u];
        }
        __syncthreads();

        if (c < 63) {
            const size_t go = (size_t)(c + 1) * 64;
            #pragma unroll
            for (int u = 0; u < 4; u++) {
                rp[u] = reinterpret_cast<const uint4*>(pS + go)[u];
                rv[u] = reinterpret_cast<const uint4*>(vS + go)[u];
            }
        }

        #pragma unroll
        for (int kk = 0; kk < 4; kk++) {
            unsigned aH[2][4], bH[2][4], bL[2][4];
            #pragma unroll
            for (int mt = 0; mt < 2; mt++) {
                const unsigned ad = base + PH + aoff + mt * 2304 + kk * 32;
                ldsm4(aH[mt][0], aH[mt][1], aH[mt][2], aH[mt][3], ad);
            }
            #pragma unroll
            for (int g = 0; g < 2; g++) {
                const unsigned bd = base + VH + boff + g * 2304 + kk * 32;
                ldsm4(bH[g][0], bH[g][1], bH[g][2], bH[g][3], bd);
                ldsm4(bL[g][0], bL[g][1], bL[g][2], bL[g][3], bd + (VL - VH));
            }
            #pragma unroll
            for (int mt = 0; mt < 2; mt++)
                #pragma unroll
                for (int nt = 0; nt < 4; nt++) {
                    mma_f16(acc[mt][nt], aH[mt], &bH[nt >> 1][(nt & 1) * 2]);
                    mma_f16(acc[mt][nt], aH[mt], &bL[nt >> 1][(nt & 1) * 2]);
                }
        }
        __syncthreads();
    }

    #pragma unroll
    for (int mt = 0; mt < 2; mt++) {
        const int row0 = i0 + wm * 32 + mt * 16 + qr;
        #pragma unroll
        for (int nt = 0; nt < 4; nt++) {
            const int col = h * DKk + wn * 32 + nt * 8 + qc * 2;
            #pragma unroll
            for (int pr = 0; pr < 2; pr++) {
                float2 o = make_float2(acc[mt][nt][pr * 2] * OSCALE,
                                       acc[mt][nt][pr * 2 + 1] * OSCALE);
                *reinterpret_cast<float2*>(
                    att + ((size_t)(b * Ss + row0 + pr * 8)) * Gg + col) = o;
            }
        }
    }
}

// ---------------------------------------------------------------------------
extern "C" void kernel_launch(void* const* d_in, const int* in_sizes, int n_in,
                              void* d_out, int out_size)
{
    const float* x  = (const float*)d_in[0];
    const float* wq = (const float*)d_in[1];
    const float* bq = (const float*)d_in[2];
    const float* wk = (const float*)d_in[3];
    const float* bk = (const float*)d_in[4];
    const float* wv = (const float*)d_in[5];
    const float* bv = (const float*)d_in[6];
    const float* wo = (const float*)d_in[7];
    const float* bo = (const float*)d_in[8];
    float* out = (float*)d_out;

    __nv_bfloat16 *xh, *xl, *wh, *wl, *qhi, *qlo, *khi, *klo, *atth, *attl;
    __half *p, *vthi, *vtlo;
    float *v, *part, *winv, *att;
    cudaGetSymbolAddress((void**)&xh,  g_xh);   cudaGetSymbolAddress((void**)&xl,  g_xl);
    cudaGetSymbolAddress((void**)&wh,  g_wh);   cudaGetSymbolAddress((void**)&wl,  g_wl);
    cudaGetSymbolAddress((void**)&qhi, g_qhi);  cudaGetSymbolAddress((void**)&qlo, g_qlo);
    cudaGetSymbolAddress((void**)&khi, g_khi);  cudaGetSymbolAddress((void**)&klo, g_klo);
    cudaGetSymbolAddress((void**)&v,   g_v);
    cudaGetSymbolAddress((void**)&p,   g_p);
    cudaGetSymbolAddress((void**)&part,g_part); cudaGetSymbolAddress((void**)&winv,g_winv);
    cudaGetSymbolAddress((void**)&vthi,g_vthi); cudaGetSymbolAddress((void**)&vtlo,g_vtlo);
    cudaGetSymbolAddress((void**)&att, g_att);
    cudaGetSymbolAddress((void**)&atth,g_atth); cudaGetSymbolAddress((void**)&attl,g_attl);

    const int SC_SMEM = 73728;
    const int PV_SMEM = 36864;
    const int TC_SMEM = 55552;
    cudaFuncSetAttribute(scores_wm_kernel, cudaFuncAttributeMaxDynamicSharedMemorySize, SC_SMEM);
    cudaFuncSetAttribute(pv_wm_kernel,     cudaFuncAttributeMaxDynamicSharedMemorySize, PV_SMEM);
    cudaFuncSetAttribute(gemm_tc_kernel<0>, cudaFuncAttributeMaxDynamicSharedMemorySize, TC_SMEM);
    cudaFuncSetAttribute(gemm_tc_kernel<1>, cudaFuncAttributeMaxDynamicSharedMemorySize, TC_SMEM);

    const int WN = Gg * Gg;                 // 65536

    // splits
    split_x_kernel<<<6144, 256>>>(x, xh, xl);
    split1_kernel<<<64, 256>>>(wq, wh + 0 * WN, wl + 0 * WN, WN / 4);
    split1_kernel<<<64, 256>>>(wk, wh + 1 * WN, wl + 1 * WN, WN / 4);
    split1_kernel<<<64, 256>>>(wv, wh + 2 * WN, wl + 2 * WN, WN / 4);
    split1_kernel<<<64, 256>>>(wo, wh + 3 * WN, wl + 3 * WN, WN / 4);

    // projections (tensor cores)
    dim3 gTC(4, 64);
    gemm_tc_kernel<1><<<gTC, 256, TC_SMEM>>>(xh + 0 * NSG, xl + 0 * NSG,
        wh + 0 * WN, wl + 0 * WN, bq, nullptr, qhi, qlo);
    gemm_tc_kernel<1><<<gTC, 256, TC_SMEM>>>(xh + 1 * NSG, xl + 1 * NSG,
        wh + 1 * WN, wl + 1 * WN, bk, nullptr, khi, klo);
    gemm_tc_kernel<0><<<gTC, 256, TC_SMEM>>>(xh + 2 * NSG, xl + 2 * NSG,
        wh + 2 * WN, wl + 2 * WN, bv, v, nullptr, nullptr);

    // attention
    scores_wm_kernel<<<dim3(32, 32, 8), 256, SC_SMEM>>>(qhi, qlo, khi, klo, p, part);
    colsum_final_kernel<<<dim3(16, 8), 256>>>(part, winv);
    scale_v_t_kernel<<<dim3(64, 8), 256>>>(v, winv, vthi, vtlo);
    pv_wm_kernel<<<dim3(32, 8), 256, PV_SMEM>>>(p, vthi, vtlo, att);

    // out projection (tensor cores)
    split1_kernel<<<2048, 256>>>(att, atth, attl, NSG / 4);
    gemm_tc_kernel<0><<<gTC, 256, TC_SMEM>>>(atth, attl,
        wh + 3 * WN, wl + 3 * WN, bo, out, nullptr, nullptr);
}

// round 8
// speedup vs baseline: 3.1690x; 1.1590x over previous
#include <cuda_runtime.h>
#include <cuda_bf16.h>
#include <cuda_fp16.h>
#include <math.h>

#define Bb   2
#define Ss   4096
#define Gg   256
#define Hh   4
#define DKk  64
#define DIMd 768
#define EXP2K (0.125f * 1.44269504088896341f)
#define VSCALE 4096.0f
#define OSCALE (1.0f / 4096.0f)
#define NSG (Bb * Ss * Gg)

// ---------------- scratch ----------------
__device__ __nv_bfloat16 g_xh[3 * NSG];      // x slices hi (q,k,v inputs)
__device__ __nv_bfloat16 g_xl[3 * NSG];
__device__ __nv_bfloat16 g_wh[4 * Gg * Gg];  // wq,wk,wv,wo hi
__device__ __nv_bfloat16 g_wl[4 * Gg * Gg];
__device__ __half g_q16[NSG];                // Q fp16
__device__ __half g_k16[NSG];                // K fp16
__device__ float  g_v  [NSG];
__device__ __half g_p[(size_t)Bb * Hh * Ss * Ss];            // 268 MB, fp16
__device__ float g_part[(size_t)Bb * Hh * 64 * Ss];
__device__ float g_winv[Bb * Hh * Ss];
__device__ __half g_vthi[Bb * Hh * DKk * Ss];
__device__ __half g_vtlo[Bb * Hh * DKk * Ss];
__device__ float g_att[NSG];
__device__ __nv_bfloat16 g_atth[NSG];
__device__ __nv_bfloat16 g_attl[NSG];

// ---------------- helpers ----------------
__device__ __forceinline__ unsigned smem_u32(const void* p) {
    unsigned a;
    asm("{ .reg .u64 t; cvta.to.shared.u64 t, %1; cvt.u32.u64 %0, t; }" : "=r"(a) : "l"(p));
    return a;
}
__device__ __forceinline__ float ex2f(float x) {
    float r;
    asm("ex2.approx.ftz.f32 %0, %1;" : "=f"(r) : "f"(x));
    return r;
}
__device__ __forceinline__ void ldsm4(unsigned& r0, unsigned& r1, unsigned& r2,
                                      unsigned& r3, unsigned addr) {
    asm volatile("ldmatrix.sync.aligned.m8n8.x4.shared.b16 {%0,%1,%2,%3}, [%4];"
                 : "=r"(r0), "=r"(r1), "=r"(r2), "=r"(r3) : "r"(addr));
}
__device__ __forceinline__ void mma_bf16(float* c, const unsigned* a, const unsigned* b) {
    asm volatile(
        "mma.sync.aligned.m16n8k16.row.col.f32.bf16.bf16.f32 "
        "{%0,%1,%2,%3},{%4,%5,%6,%7},{%8,%9},{%0,%1,%2,%3};"
        : "+f"(c[0]), "+f"(c[1]), "+f"(c[2]), "+f"(c[3])
        : "r"(a[0]), "r"(a[1]), "r"(a[2]), "r"(a[3]), "r"(b[0]), "r"(b[1]));
}
__device__ __forceinline__ void mma_f16(float* c, const unsigned* a, const unsigned* b) {
    asm volatile(
        "mma.sync.aligned.m16n8k16.row.col.f32.f16.f16.f32 "
        "{%0,%1,%2,%3},{%4,%5,%6,%7},{%8,%9},{%0,%1,%2,%3};"
        : "+f"(c[0]), "+f"(c[1]), "+f"(c[2]), "+f"(c[3])
        : "r"(a[0]), "r"(a[1]), "r"(a[2]), "r"(a[3]), "r"(b[0]), "r"(b[1]));
}
__device__ __forceinline__ void split2(float a, float b, unsigned& h, unsigned& l) {
    __nv_bfloat162 h2 = __floats2bfloat162_rn(a, b);
    __nv_bfloat162 l2 = __floats2bfloat162_rn(a - __bfloat162float(h2.x),
                                              b - __bfloat162float(h2.y));
    h = *reinterpret_cast<unsigned*>(&h2);
    l = *reinterpret_cast<unsigned*>(&l2);
}

// ---------------- split kernels ----------------
__global__ __launch_bounds__(256) void split_x_kernel(
    const float* __restrict__ x, __nv_bfloat16* __restrict__ hi,
    __nv_bfloat16* __restrict__ lo)
{
    const int i = blockIdx.x * 256 + threadIdx.x;
    float4 f = reinterpret_cast<const float4*>(x)[i];
    const int row = i / 192, c4 = i - row * 192;
    const int slice = c4 >> 6, w4 = c4 & 63;
    const size_t o = (size_t)slice * NSG + (size_t)row * Gg + w4 * 4;
    uint2 hv, lv;
    split2(f.x, f.y, hv.x, lv.x);
    split2(f.z, f.w, hv.y, lv.y);
    *reinterpret_cast<uint2*>(hi + o) = hv;
    *reinterpret_cast<uint2*>(lo + o) = lv;
}

__global__ __launch_bounds__(256) void split1_kernel(
    const float* __restrict__ src, __nv_bfloat16* __restrict__ hi,
    __nv_bfloat16* __restrict__ lo, int n4)
{
    const int i = blockIdx.x * 256 + threadIdx.x;
    if (i >= n4) return;
    float4 f = reinterpret_cast<const float4*>(src)[i];
    uint2 hv, lv;
    split2(f.x, f.y, hv.x, lv.x);
    split2(f.z, f.w, hv.y, lv.y);
    *reinterpret_cast<uint2*>(hi + (size_t)i * 4) = hv;
    *reinterpret_cast<uint2*>(lo + (size_t)i * 4) = lv;
}

// ---------------------------------------------------------------------------
// Tensor-core projection GEMM (bf16x3): C[M,256] = A[M,256] @ W[256,256]^T + b
// CTA 128x64, K=256 in 4 chunks.  8 warps 4(m) x 2(n).
// OUT=0: fp32.  OUT=2: fp16 (Q/K).  grid (4, M/128), 256 thr, smem 55552 B.
// ---------------------------------------------------------------------------
template <int OUT>
__global__ __launch_bounds__(256) void gemm_tc_kernel(
    const __nv_bfloat16* __restrict__ Ahi, const __nv_bfloat16* __restrict__ Alo,
    const __nv_bfloat16* __restrict__ Whi, const __nv_bfloat16* __restrict__ Wlo,
    const float* __restrict__ bias, float* __restrict__ C,
    __half* __restrict__ C16)
{
    extern __shared__ char sm[];
    const int AH = 0, AL = 18432, WH = 36864, WL = 46080, SBIAS = 55296;
    const int tid = threadIdx.x, lane = tid & 31, wid = tid >> 5;
    const int wm = wid >> 1, wn = wid & 1;
    const int n0 = blockIdx.x * 64, m0 = blockIdx.y * 128;
    const int qr = lane >> 2, qc = lane & 3;

    if (tid < 16)
        *reinterpret_cast<float4*>(sm + SBIAS + tid * 16) =
            *reinterpret_cast<const float4*>(bias + n0 + tid * 4);

    const int arow = tid >> 1, ahalf = tid & 1;
    const __nv_bfloat16* aH = Ahi + (size_t)(m0 + arow) * Gg + ahalf * 32;
    const __nv_bfloat16* aL = Alo + (size_t)(m0 + arow) * Gg + ahalf * 32;
    const unsigned aso = arow * 144 + ahalf * 64;
    const int wrow = tid >> 2, wq = tid & 3;
    const __nv_bfloat16* wH = Whi + (size_t)(n0 + wrow) * Gg + wq * 16;
    const __nv_bfloat16* wL = Wlo + (size_t)(n0 + wrow) * Gg + wq * 16;
    const unsigned wso = wrow * 144 + wq * 32;

    const unsigned base = smem_u32(sm);
    const unsigned aoff = (wm * 32 + (lane & 15)) * 144 + ((lane >> 4) * 8) * 2;
    const unsigned boff = (wn * 32 + ((lane >> 4) & 1) * 8 + (lane & 7)) * 144
                        + (((lane >> 3) & 1) * 8) * 2;

    float acc[2][4][4] = {};
    uint4 rah[4], ral[4], rwh[2], rwl[2];

    #pragma unroll
    for (int u = 0; u < 4; u++) {
        rah[u] = reinterpret_cast<const uint4*>(aH)[u];
        ral[u] = reinterpret_cast<const uint4*>(aL)[u];
    }
    #pragma unroll
    for (int u = 0; u < 2; u++) {
        rwh[u] = reinterpret_cast<const uint4*>(wH)[u];
        rwl[u] = reinterpret_cast<const uint4*>(wL)[u];
    }

    for (int c = 0; c < 4; c++) {
        #pragma unroll
        for (int u = 0; u < 4; u++) {
            *reinterpret_cast<uint4*>(sm + AH + aso + u * 16) = rah[u];
            *reinterpret_cast<uint4*>(sm + AL + aso + u * 16) = ral[u];
        }
        #pragma unroll
        for (int u = 0; u < 2; u++) {
            *reinterpret_cast<uint4*>(sm + WH + wso + u * 16) = rwh[u];
            *reinterpret_cast<uint4*>(sm + WL + wso + u * 16) = rwl[u];
        }
        __syncthreads();

        if (c < 3) {
            const int go = (c + 1) * 64;
            #pragma unroll
            for (int u = 0; u < 4; u++) {
                rah[u] = reinterpret_cast<const uint4*>(aH + go)[u];
                ral[u] = reinterpret_cast<const uint4*>(aL + go)[u];
            }
            #pragma unroll
            for (int u = 0; u < 2; u++) {
                rwh[u] = reinterpret_cast<const uint4*>(wH + go)[u];
                rwl[u] = reinterpret_cast<const uint4*>(wL + go)[u];
            }
        }

        #pragma unroll
        for (int kk = 0; kk < 4; kk++) {
            unsigned fah[2][4], fal[2][4], fbh[2][4], fbl[2][4];
            #pragma unroll
            for (int mt = 0; mt < 2; mt++) {
                const unsigned ad = base + AH + aoff + mt * 2304 + kk * 32;
                ldsm4(fah[mt][0], fah[mt][1], fah[mt][2], fah[mt][3], ad);
                ldsm4(fal[mt][0], fal[mt][1], fal[mt][2], fal[mt][3], ad + (AL - AH));
            }
            #pragma unroll
            for (int g = 0; g < 2; g++) {
                const unsigned bd = base + WH + boff + g * 2304 + kk * 32;
                ldsm4(fbh[g][0], fbh[g][1], fbh[g][2], fbh[g][3], bd);
                ldsm4(fbl[g][0], fbl[g][1], fbl[g][2], fbl[g][3], bd + (WL - WH));
            }
            #pragma unroll
            for (int mt = 0; mt < 2; mt++)
                #pragma unroll
                for (int nt = 0; nt < 4; nt++) {
                    const unsigned* pbh = &fbh[nt >> 1][(nt & 1) * 2];
                    const unsigned* pbl = &fbl[nt >> 1][(nt & 1) * 2];
                    mma_bf16(acc[mt][nt], fah[mt], pbh);
                    mma_bf16(acc[mt][nt], fah[mt], pbl);
                    mma_bf16(acc[mt][nt], fal[mt], pbh);
                }
        }
        __syncthreads();
    }

    const float* bs = reinterpret_cast<const float*>(sm + SBIAS);
    if (OUT == 2) {
        __half* sh = reinterpret_cast<__half*>(sm);                 // stride 72
        #pragma unroll
        for (int mt = 0; mt < 2; mt++) {
            const int r0 = wm * 32 + mt * 16 + qr;
            #pragma unroll
            for (int nt = 0; nt < 4; nt++) {
                const int col = wn * 32 + nt * 8 + qc * 2;
                #pragma unroll
                for (int pr = 0; pr < 2; pr++) {
                    __half2 h2 = __floats2half2_rn(acc[mt][nt][pr * 2]     + bs[col],
                                                   acc[mt][nt][pr * 2 + 1] + bs[col + 1]);
                    *reinterpret_cast<__half2*>(sh + (r0 + pr * 8) * 72 + col) = h2;
                }
            }
        }
        __syncthreads();
        #pragma unroll
        for (int ps = 0; ps < 4; ps++) {
            const int idx = ps * 2048 + tid * 8;
            const int row = idx >> 6, col = idx & 63;
            uint4 hv = *reinterpret_cast<const uint4*>(sh + row * 72 + col);
            *reinterpret_cast<uint4*>(C16 + (size_t)(m0 + row) * Gg + n0 + col) = hv;
        }
    } else {
        float* sc = reinterpret_cast<float*>(sm);                    // stride 68
        #pragma unroll
        for (int mt = 0; mt < 2; mt++) {
            const int r0 = wm * 32 + mt * 16 + qr;
            #pragma unroll
            for (int nt = 0; nt < 4; nt++) {
                const int col = wn * 32 + nt * 8 + qc * 2;
                #pragma unroll
                for (int pr = 0; pr < 2; pr++) {
                    float2 o = make_float2(acc[mt][nt][pr * 2]     + bs[col],
                                           acc[mt][nt][pr * 2 + 1] + bs[col + 1]);
                    *reinterpret_cast<float2*>(sc + (r0 + pr * 8) * 68 + col) = o;
                }
            }
        }
        __syncthreads();
        #pragma unroll
        for (int ps = 0; ps < 8; ps++) {
            const int idx = ps * 1024 + tid * 4;
            const int row = idx >> 6, col = idx & 63;
            float4 v = *reinterpret_cast<const float4*>(sc + row * 68 + col);
            *reinterpret_cast<float4*>(C + (size_t)(m0 + row) * Gg + n0 + col) = v;
        }
    }
}

// ---------------------------------------------------------------------------
// scores: P(fp16) = exp(scale*QK^T), SINGLE-pass fp16 MMA.  CTA 128x128, K=64.
// 8 warps 2(m) x 4(n).  Fused fp32 column sums; staged coalesced P store.
// grid (32,32,8), 256 thr, dyn smem 71680 B.
// ---------------------------------------------------------------------------
__global__ __launch_bounds__(256) void scores_wm_kernel(
    const __half* __restrict__ Q, const __half* __restrict__ Kt,
    __half* __restrict__ P, float* __restrict__ part)
{
    extern __shared__ char sm[];
    const int QH = 0, KH = 18432, STG_BASE = 36864;
    const int tid = threadIdx.x, lane = tid & 31, wid = tid >> 5;
    const int wm = wid >> 2, wn = wid & 3;
    const int bh = blockIdx.z, b = bh >> 2, h = bh & 3;
    const int i0 = blockIdx.y * 128, j0 = blockIdx.x * 128;

    {
        const int row = tid >> 1, half = tid & 1;
        const size_t qoff = ((size_t)(b * Ss + i0 + row)) * Gg + h * DKk + half * 32;
        const size_t koff = ((size_t)(b * Ss + j0 + row)) * Gg + h * DKk + half * 32;
        const unsigned so = row * 144 + half * 64;
        const uint4* q1 = reinterpret_cast<const uint4*>(Q + qoff);
        const uint4* k1 = reinterpret_cast<const uint4*>(Kt + koff);
        #pragma unroll
        for (int u = 0; u < 4; u++) {
            *reinterpret_cast<uint4*>(sm + QH + so + u * 16) = q1[u];
            *reinterpret_cast<uint4*>(sm + KH + so + u * 16) = k1[u];
        }
    }
    __syncthreads();

    const unsigned base = smem_u32(sm);
    const int qr = lane >> 2, qc = lane & 3;
    const unsigned aoff = (wm * 64 + (lane & 15)) * 144 + ((lane >> 4) * 8) * 2;
    const unsigned boff = (wn * 32 + ((lane >> 4) & 1) * 8 + (lane & 7)) * 144
                        + (((lane >> 3) & 1) * 8) * 2;

    float acc[4][4][4] = {};
    #pragma unroll
    for (int kk = 0; kk < 4; kk++) {
        unsigned aH[4][4], bH[2][4];
        #pragma unroll
        for (int mt = 0; mt < 4; mt++) {
            const unsigned ad = base + QH + aoff + mt * 2304 + kk * 32;
            ldsm4(aH[mt][0], aH[mt][1], aH[mt][2], aH[mt][3], ad);
        }
        #pragma unroll
        for (int g = 0; g < 2; g++) {
            const unsigned bd = base + KH + boff + g * 2304 + kk * 32;
            ldsm4(bH[g][0], bH[g][1], bH[g][2], bH[g][3], bd);
        }
        #pragma unroll
        for (int mt = 0; mt < 4; mt++)
            #pragma unroll
            for (int nt = 0; nt < 4; nt++)
                mma_f16(acc[mt][nt], aH[mt], &bH[nt >> 1][(nt & 1) * 2]);
    }

    #pragma unroll
    for (int mt = 0; mt < 4; mt++)
        #pragma unroll
        for (int nt = 0; nt < 4; nt++)
            #pragma unroll
            for (int r = 0; r < 4; r++)
                acc[mt][nt][r] = ex2f(acc[mt][nt][r] * EXP2K);

    const int jbase = j0 + wn * 32;
    #pragma unroll
    for (int nt = 0; nt < 4; nt++) {
        #pragma unroll
        for (int p = 0; p < 2; p++) {
            float s = 0.f;
            #pragma unroll
            for (int mt = 0; mt < 4; mt++) s += acc[mt][nt][p] + acc[mt][nt][p + 2];
            #pragma unroll
            for (int o = 4; o < 32; o <<= 1) s += __shfl_xor_sync(0xffffffffu, s, o);
            if (qr == 0)
                part[((size_t)(bh * 32 + blockIdx.y) * 2 + wm) * Ss
                     + jbase + nt * 8 + qc * 2 + p] = s;
        }
    }

    __syncthreads();
    __half* stg = reinterpret_cast<__half*>(sm + STG_BASE);
    #pragma unroll
    for (int mt = 0; mt < 4; mt++) {
        const int r0 = wm * 64 + mt * 16 + qr;
        #pragma unroll
        for (int nt = 0; nt < 4; nt++) {
            const int col = wn * 32 + nt * 8 + qc * 2;
            #pragma unroll
            for (int pr = 0; pr < 2; pr++) {
                __half2 h2 = __floats2half2_rn(acc[mt][nt][pr * 2],
                                               acc[mt][nt][pr * 2 + 1]);
                *reinterpret_cast<__half2*>(stg + (r0 + pr * 8) * 136 + col) = h2;
            }
        }
    }
    __syncthreads();
    {
        const size_t pb = ((size_t)bh * Ss + i0) * Ss + j0;
        #pragma unroll
        for (int ps = 0; ps < 8; ps++) {
            const int el = ps * 2048 + tid * 8;
            const int row = el >> 7, col = el & 127;
            uint4 vv = *reinterpret_cast<const uint4*>(stg + row * 136 + col);
            *reinterpret_cast<uint4*>(P + pb + (size_t)row * Ss + col) = vv;
        }
    }
}

// winv[bh,j] = 1/sum_{c<64} part[bh*64+c, j].  grid (16,8) x 256
__global__ __launch_bounds__(256) void colsum_final_kernel(
    const float* __restrict__ part, float* __restrict__ winv)
{
    const int j = blockIdx.x * 256 + threadIdx.x;
    const int bh = blockIdx.y;
    const float* p = part + (size_t)bh * 64 * Ss + j;
    float s = 0.f;
    #pragma unroll 8
    for (int c = 0; c < 64; c++) s += p[(size_t)c * Ss];
    winv[(size_t)bh * Ss + j] = 1.0f / s;
}

// vT[bh,d,j] = v[b,j,h*64+d]*winv[bh,j]*4096 -> fp16 hi/lo.  grid (64,8) x 256
__global__ __launch_bounds__(256) void scale_v_t_kernel(
    const float* __restrict__ v, const float* __restrict__ winv,
    __half* __restrict__ tH, __half* __restrict__ tL)
{
    __shared__ float ts[64][65];
    const int tid = threadIdx.x, bh = blockIdx.y, b = bh >> 2, h = bh & 3;
    const int j0 = blockIdx.x * 64;
    {
        const int j = tid >> 2, c0 = (tid & 3) * 16;
        const float* src = v + ((size_t)(b * Ss + j0 + j)) * Gg + h * DKk + c0;
        #pragma unroll
        for (int u = 0; u < 4; u++) {
            float4 f = *reinterpret_cast<const float4*>(src + u * 4);
            ts[j][c0 + 4*u]     = f.x; ts[j][c0 + 4*u + 1] = f.y;
            ts[j][c0 + 4*u + 2] = f.z; ts[j][c0 + 4*u + 3] = f.w;
        }
    }
    __syncthreads();
    const int d = tid >> 2, jj0 = (tid & 3) * 16;
    const size_t ob = (((size_t)bh) * DKk + d) * Ss + j0 + jj0;
    const float* wv = winv + (size_t)bh * Ss + j0 + jj0;
    __half hbuf[16], lbuf[16];
    #pragma unroll
    for (int u = 0; u < 16; u++) {
        float f = ts[jj0 + u][d] * wv[u] * VSCALE;
        __half hb = __float2half_rn(f);
        hbuf[u] = hb;
        lbuf[u] = __float2half_rn(f - __half2float(hb));
    }
    #pragma unroll
    for (int u = 0; u < 2; u++) {
        *reinterpret_cast<uint4*>(tH + ob + u * 8) = reinterpret_cast<uint4*>(hbuf)[u];
        *reinterpret_cast<uint4*>(tL + ob + u * 8) = reinterpret_cast<uint4*>(lbuf)[u];
    }
}

// ---------------------------------------------------------------------------
// pv: Att = (P @ Vw^T)/4096, fp16 MMA, 2 passes (Vhi, Vlo).  (unchanged)
// ---------------------------------------------------------------------------
__global__ __launch_bounds__(256) void pv_wm_kernel(
    const __half* __restrict__ P, const __half* __restrict__ vthi,
    const __half* __restrict__ vtlo, float* __restrict__ att)
{
    extern __shared__ char sm[];
    const int PH = 0, VH = 18432, VL = 27648;
    const int tid = threadIdx.x, lane = tid & 31, wid = tid >> 5;
    const int wm = wid >> 1, wn = wid & 1;
    const int bh = blockIdx.y, b = bh >> 2, h = bh & 3;
    const int i0 = blockIdx.x * 128;
    const int qr = lane >> 2, qc = lane & 3;

    const int prow = tid >> 1, phalf = tid & 1;
    const __half* pS = P + ((size_t)bh * Ss + i0 + prow) * Ss + phalf * 32;
    const unsigned pso = prow * 144 + phalf * 64;
    const int vtile = tid >> 7, vrow = (tid >> 1) & 63, vhalf = tid & 1;
    const __half* vS = (vtile ? vtlo : vthi)
                     + ((size_t)bh * DKk + vrow) * Ss + vhalf * 32;
    const unsigned vso = (vtile ? VL : VH) + vrow * 144 + vhalf * 64;

    const unsigned base = smem_u32(sm);
    const unsigned aoff = (wm * 32 + (lane & 15)) * 144 + ((lane >> 4) * 8) * 2;
    const unsigned boff = (wn * 32 + ((lane >> 4) & 1) * 8 + (lane & 7)) * 144
                        + (((lane >> 3) & 1) * 8) * 2;

    float acc[2][4][4] = {};
    uint4 rp[4], rv[4];

    #pragma unroll
    for (int u = 0; u < 4; u++) {
        rp[u] = reinterpret_cast<const uint4*>(pS)[u];
        rv[u] = reinterpret_cast<const uint4*>(vS)[u];
    }

    for (int c = 0; c < 64; c++) {
        #pragma unroll
        for (int u = 0; u < 4; u++) {
            *reinterpret_cast<uint4*>(sm + PH + pso + u * 16) = rp[u];
            *reinterpret_cast<uint4*>(sm + vso + u * 16)      = rv[u];
        }
        __syncthreads();

        if (c < 63) {
            const size_t go = (size_t)(c + 1) * 64;
            #pragma unroll
            for (int u = 0; u < 4; u++) {
                rp[u] = reinterpret_cast<const uint4*>(pS + go)[u];
                rv[u] = reinterpret_cast<const uint4*>(vS + go)[u];
            }
        }

        #pragma unroll
        for (int kk = 0; kk < 4; kk++) {
            unsigned aH[2][4], bH[2][4], bL[2][4];
            #pragma unroll
            for (int mt = 0; mt < 2; mt++) {
                const unsigned ad = base + PH + aoff + mt * 2304 + kk * 32;
                ldsm4(aH[mt][0], aH[mt][1], aH[mt][2], aH[mt][3], ad);
            }
            #pragma unroll
            for (int g = 0; g < 2; g++) {
                const unsigned bd = base + VH + boff + g * 2304 + kk * 32;
                ldsm4(bH[g][0], bH[g][1], bH[g][2], bH[g][3], bd);
                ldsm4(bL[g][0], bL[g][1], bL[g][2], bL[g][3], bd + (VL - VH));
            }
            #pragma unroll
            for (int mt = 0; mt < 2; mt++)
                #pragma unroll
                for (int nt = 0; nt < 4; nt++) {
                    mma_f16(acc[mt][nt], aH[mt], &bH[nt >> 1][(nt & 1) * 2]);
                    mma_f16(acc[mt][nt], aH[mt], &bL[nt >> 1][(nt & 1) * 2]);
                }
        }
        __syncthreads();
    }

    #pragma unroll
    for (int mt = 0; mt < 2; mt++) {
        const int row0 = i0 + wm * 32 + mt * 16 + qr;
        #pragma unroll
        for (int nt = 0; nt < 4; nt++) {
            const int col = h * DKk + wn * 32 + nt * 8 + qc * 2;
            #pragma unroll
            for (int pr = 0; pr < 2; pr++) {
                float2 o = make_float2(acc[mt][nt][pr * 2] * OSCALE,
                                       acc[mt][nt][pr * 2 + 1] * OSCALE);
                *reinterpret_cast<float2*>(
                    att + ((size_t)(b * Ss + row0 + pr * 8)) * Gg + col) = o;
            }
        }
    }
}

// ---------------------------------------------------------------------------
extern "C" void kernel_launch(void* const* d_in, const int* in_sizes, int n_in,
                              void* d_out, int out_size)
{
    const float* x  = (const float*)d_in[0];
    const float* wq = (const float*)d_in[1];
    const float* bq = (const float*)d_in[2];
    const float* wk = (const float*)d_in[3];
    const float* bk = (const float*)d_in[4];
    const float* wv = (const float*)d_in[5];
    const float* bv = (const float*)d_in[6];
    const float* wo = (const float*)d_in[7];
    const float* bo = (const float*)d_in[8];
    float* out = (float*)d_out;

    __nv_bfloat16 *xh, *xl, *wh, *wl, *atth, *attl;
    __half *q16, *k16, *p, *vthi, *vtlo;
    float *v, *part, *winv, *att;
    cudaGetSymbolAddress((void**)&xh,  g_xh);   cudaGetSymbolAddress((void**)&xl,  g_xl);
    cudaGetSymbolAddress((void**)&wh,  g_wh);   cudaGetSymbolAddress((void**)&wl,  g_wl);
    cudaGetSymbolAddress((void**)&q16, g_q16);  cudaGetSymbolAddress((void**)&k16, g_k16);
    cudaGetSymbolAddress((void**)&v,   g_v);
    cudaGetSymbolAddress((void**)&p,   g_p);
    cudaGetSymbolAddress((void**)&part,g_part); cudaGetSymbolAddress((void**)&winv,g_winv);
    cudaGetSymbolAddress((void**)&vthi,g_vthi); cudaGetSymbolAddress((void**)&vtlo,g_vtlo);
    cudaGetSymbolAddress((void**)&att, g_att);
    cudaGetSymbolAddress((void**)&atth,g_atth); cudaGetSymbolAddress((void**)&attl,g_attl);

    const int SC_SMEM = 71680;
    const int PV_SMEM = 36864;
    const int TC_SMEM = 55552;
    cudaFuncSetAttribute(scores_wm_kernel, cudaFuncAttributeMaxDynamicSharedMemorySize, SC_SMEM);
    cudaFuncSetAttribute(pv_wm_kernel,     cudaFuncAttributeMaxDynamicSharedMemorySize, PV_SMEM);
    cudaFuncSetAttribute(gemm_tc_kernel<0>, cudaFuncAttributeMaxDynamicSharedMemorySize, TC_SMEM);
    cudaFuncSetAttribute(gemm_tc_kernel<2>, cudaFuncAttributeMaxDynamicSharedMemorySize, TC_SMEM);

    const int WN = Gg * Gg;                 // 65536

    // splits
    split_x_kernel<<<6144, 256>>>(x, xh, xl);
    split1_kernel<<<64, 256>>>(wq, wh + 0 * WN, wl + 0 * WN, WN / 4);
    split1_kernel<<<64, 256>>>(wk, wh + 1 * WN, wl + 1 * WN, WN / 4);
    split1_kernel<<<64, 256>>>(wv, wh + 2 * WN, wl + 2 * WN, WN / 4);
    split1_kernel<<<64, 256>>>(wo, wh + 3 * WN, wl + 3 * WN, WN / 4);

    // projections (tensor cores)
    dim3 gTC(4, 64);
    gemm_tc_kernel<2><<<gTC, 256, TC_SMEM>>>(xh + 0 * NSG, xl + 0 * NSG,
        wh + 0 * WN, wl + 0 * WN, bq, nullptr, q16);
    gemm_tc_kernel<2><<<gTC, 256, TC_SMEM>>>(xh + 1 * NSG, xl + 1 * NSG,
        wh + 1 * WN, wl + 1 * WN, bk, nullptr, k16);
    gemm_tc_kernel<0><<<gTC, 256, TC_SMEM>>>(xh + 2 * NSG, xl + 2 * NSG,
        wh + 2 * WN, wl + 2 * WN, bv, v, nullptr);

    // attention
    scores_wm_kernel<<<dim3(32, 32, 8), 256, SC_SMEM>>>(q16, k16, p, part);
    colsum_final_kernel<<<dim3(16, 8), 256>>>(part, winv);
    scale_v_t_kernel<<<dim3(64, 8), 256>>>(v, winv, vthi, vtlo);
    pv_wm_kernel<<<dim3(32, 8), 256, PV_SMEM>>>(p, vthi, vtlo, att);

    // out projection (tensor cores)
    split1_kernel<<<2048, 256>>>(att, atth, attl, NSG / 4);
    gemm_tc_kernel<0><<<gTC, 256, TC_SMEM>>>(atth, attl,
        wh + 3 * WN, wl + 3 * WN, bo, out, nullptr);
}

// round 9
// speedup vs baseline: 3.6347x; 1.1470x over previous
#include <cuda_runtime.h>
#include <cuda_bf16.h>
#include <cuda_fp16.h>
#include <math.h>

#define Bb   2
#define Ss   4096
#define Gg   256
#define Hh   4
#define DKk  64
#define DIMd 768
#define EXP2K (0.125f * 1.44269504088896341f)
#define VSCALE 4096.0f
#define OSCALE (1.0f / 4096.0f)
#define NSG (Bb * Ss * Gg)

// ---------------- scratch ----------------
__device__ __nv_bfloat16 g_xh[3 * NSG];
__device__ __nv_bfloat16 g_xl[3 * NSG];
__device__ __nv_bfloat16 g_wh[4 * Gg * Gg];
__device__ __nv_bfloat16 g_wl[4 * Gg * Gg];
__device__ __half g_q16[NSG];
__device__ __half g_k16[NSG];
__device__ float  g_v  [NSG];
__device__ __half g_p[(size_t)Bb * Hh * Ss * Ss];            // 268 MB
__device__ float g_part[(size_t)Bb * Hh * 64 * Ss];
__device__ float g_winv[Bb * Hh * Ss];
__device__ __half g_vt[Bb * Hh * DKk * Ss];                  // (V^T*winv*4096) fp16
__device__ float g_att[NSG];
__device__ __nv_bfloat16 g_atth[NSG];
__device__ __nv_bfloat16 g_attl[NSG];

// ---------------- helpers ----------------
__device__ __forceinline__ unsigned smem_u32(const void* p) {
    unsigned a;
    asm("{ .reg .u64 t; cvta.to.shared.u64 t, %1; cvt.u32.u64 %0, t; }" : "=r"(a) : "l"(p));
    return a;
}
__device__ __forceinline__ float ex2f(float x) {
    float r;
    asm("ex2.approx.ftz.f32 %0, %1;" : "=f"(r) : "f"(x));
    return r;
}
__device__ __forceinline__ void ldsm4(unsigned& r0, unsigned& r1, unsigned& r2,
                                      unsigned& r3, unsigned addr) {
    asm volatile("ldmatrix.sync.aligned.m8n8.x4.shared.b16 {%0,%1,%2,%3}, [%4];"
                 : "=r"(r0), "=r"(r1), "=r"(r2), "=r"(r3) : "r"(addr));
}
__device__ __forceinline__ void mma_bf16(float* c, const unsigned* a, const unsigned* b) {
    asm volatile(
        "mma.sync.aligned.m16n8k16.row.col.f32.bf16.bf16.f32 "
        "{%0,%1,%2,%3},{%4,%5,%6,%7},{%8,%9},{%0,%1,%2,%3};"
        : "+f"(c[0]), "+f"(c[1]), "+f"(c[2]), "+f"(c[3])
        : "r"(a[0]), "r"(a[1]), "r"(a[2]), "r"(a[3]), "r"(b[0]), "r"(b[1]));
}
__device__ __forceinline__ void mma_f16(float* c, const unsigned* a, const unsigned* b) {
    asm volatile(
        "mma.sync.aligned.m16n8k16.row.col.f32.f16.f16.f32 "
        "{%0,%1,%2,%3},{%4,%5,%6,%7},{%8,%9},{%0,%1,%2,%3};"
        : "+f"(c[0]), "+f"(c[1]), "+f"(c[2]), "+f"(c[3])
        : "r"(a[0]), "r"(a[1]), "r"(a[2]), "r"(a[3]), "r"(b[0]), "r"(b[1]));
}
__device__ __forceinline__ void split2(float a, float b, unsigned& h, unsigned& l) {
    __nv_bfloat162 h2 = __floats2bfloat162_rn(a, b);
    __nv_bfloat162 l2 = __floats2bfloat162_rn(a - __bfloat162float(h2.x),
                                              b - __bfloat162float(h2.y));
    h = *reinterpret_cast<unsigned*>(&h2);
    l = *reinterpret_cast<unsigned*>(&l2);
}

// ---------------- split kernels ----------------
__global__ __launch_bounds__(256) void split_x_kernel(
    const float* __restrict__ x, __nv_bfloat16* __restrict__ hi,
    __nv_bfloat16* __restrict__ lo)
{
    const int i = blockIdx.x * 256 + threadIdx.x;
    float4 f = reinterpret_cast<const float4*>(x)[i];
    const int row = i / 192, c4 = i - row * 192;
    const int slice = c4 >> 6, w4 = c4 & 63;
    const size_t o = (size_t)slice * NSG + (size_t)row * Gg + w4 * 4;
    uint2 hv, lv;
    split2(f.x, f.y, hv.x, lv.x);
    split2(f.z, f.w, hv.y, lv.y);
    *reinterpret_cast<uint2*>(hi + o) = hv;
    *reinterpret_cast<uint2*>(lo + o) = lv;
}

__global__ __launch_bounds__(256) void split1_kernel(
    const float* __restrict__ src, __nv_bfloat16* __restrict__ hi,
    __nv_bfloat16* __restrict__ lo, int n4)
{
    const int i = blockIdx.x * 256 + threadIdx.x;
    if (i >= n4) return;
    float4 f = reinterpret_cast<const float4*>(src)[i];
    uint2 hv, lv;
    split2(f.x, f.y, hv.x, lv.x);
    split2(f.z, f.w, hv.y, lv.y);
    *reinterpret_cast<uint2*>(hi + (size_t)i * 4) = hv;
    *reinterpret_cast<uint2*>(lo + (size_t)i * 4) = lv;
}

// ---------------------------------------------------------------------------
// Shared bf16x3 GEMM mainloop body: acc += A[M,256] @ W[256,256]^T on 128x64
// CTA tile, K in 4 chunks, 8 warps 4(m) x 2(n).
// ---------------------------------------------------------------------------
__device__ __forceinline__ void gemm_mainloop(
    char* sm, const __nv_bfloat16* Ahi, const __nv_bfloat16* Alo,
    const __nv_bfloat16* Whi, const __nv_bfloat16* Wlo,
    int m0, int n0, float acc[2][4][4])
{
    const int AH = 0, AL = 18432, WH = 36864, WL = 46080;
    const int tid = threadIdx.x, lane = tid & 31, wid = tid >> 5;
    const int wm = wid >> 1, wn = wid & 1;

    const int arow = tid >> 1, ahalf = tid & 1;
    const __nv_bfloat16* aH = Ahi + (size_t)(m0 + arow) * Gg + ahalf * 32;
    const __nv_bfloat16* aL = Alo + (size_t)(m0 + arow) * Gg + ahalf * 32;
    const unsigned aso = arow * 144 + ahalf * 64;
    const int wrow = tid >> 2, wq = tid & 3;
    const __nv_bfloat16* wH = Whi + (size_t)(n0 + wrow) * Gg + wq * 16;
    const __nv_bfloat16* wL = Wlo + (size_t)(n0 + wrow) * Gg + wq * 16;
    const unsigned wso = wrow * 144 + wq * 32;

    const unsigned base = smem_u32(sm);
    const unsigned aoff = (wm * 32 + (lane & 15)) * 144 + ((lane >> 4) * 8) * 2;
    const unsigned boff = (wn * 32 + ((lane >> 4) & 1) * 8 + (lane & 7)) * 144
                        + (((lane >> 3) & 1) * 8) * 2;

    uint4 rah[4], ral[4], rwh[2], rwl[2];
    #pragma unroll
    for (int u = 0; u < 4; u++) {
        rah[u] = reinterpret_cast<const uint4*>(aH)[u];
        ral[u] = reinterpret_cast<const uint4*>(aL)[u];
    }
    #pragma unroll
    for (int u = 0; u < 2; u++) {
        rwh[u] = reinterpret_cast<const uint4*>(wH)[u];
        rwl[u] = reinterpret_cast<const uint4*>(wL)[u];
    }

    for (int c = 0; c < 4; c++) {
        #pragma unroll
        for (int u = 0; u < 4; u++) {
            *reinterpret_cast<uint4*>(sm + AH + aso + u * 16) = rah[u];
            *reinterpret_cast<uint4*>(sm + AL + aso + u * 16) = ral[u];
        }
        #pragma unroll
        for (int u = 0; u < 2; u++) {
            *reinterpret_cast<uint4*>(sm + WH + wso + u * 16) = rwh[u];
            *reinterpret_cast<uint4*>(sm + WL + wso + u * 16) = rwl[u];
        }
        __syncthreads();

        if (c < 3) {
            const int go = (c + 1) * 64;
            #pragma unroll
            for (int u = 0; u < 4; u++) {
                rah[u] = reinterpret_cast<const uint4*>(aH + go)[u];
                ral[u] = reinterpret_cast<const uint4*>(aL + go)[u];
            }
            #pragma unroll
            for (int u = 0; u < 2; u++) {
                rwh[u] = reinterpret_cast<const uint4*>(wH + go)[u];
                rwl[u] = reinterpret_cast<const uint4*>(wL + go)[u];
            }
        }

        #pragma unroll
        for (int kk = 0; kk < 4; kk++) {
            unsigned fah[2][4], fal[2][4], fbh[2][4], fbl[2][4];
            #pragma unroll
            for (int mt = 0; mt < 2; mt++) {
                const unsigned ad = base + AH + aoff + mt * 2304 + kk * 32;
                ldsm4(fah[mt][0], fah[mt][1], fah[mt][2], fah[mt][3], ad);
                ldsm4(fal[mt][0], fal[mt][1], fal[mt][2], fal[mt][3], ad + (AL - AH));
            }
            #pragma unroll
            for (int g = 0; g < 2; g++) {
                const unsigned bd = base + WH + boff + g * 2304 + kk * 32;
                ldsm4(fbh[g][0], fbh[g][1], fbh[g][2], fbh[g][3], bd);
                ldsm4(fbl[g][0], fbl[g][1], fbl[g][2], fbl[g][3], bd + (WL - WH));
            }
            #pragma unroll
            for (int mt = 0; mt < 2; mt++)
                #pragma unroll
                for (int nt = 0; nt < 4; nt++) {
                    const unsigned* pbh = &fbh[nt >> 1][(nt & 1) * 2];
                    const unsigned* pbl = &fbl[nt >> 1][(nt & 1) * 2];
                    mma_bf16(acc[mt][nt], fah[mt], pbh);
                    mma_bf16(acc[mt][nt], fah[mt], pbl);
                    mma_bf16(acc[mt][nt], fal[mt], pbh);
                }
        }
        __syncthreads();
    }
}

// Batched QKV projection: blockIdx.z = 0(Q,fp16), 1(K,fp16), 2(V,fp32).
// grid (4, 64, 3), 256 thr, smem 55552 B.
__global__ __launch_bounds__(256) void gemm_qkv_kernel(
    const __nv_bfloat16* __restrict__ xh, const __nv_bfloat16* __restrict__ xl,
    const __nv_bfloat16* __restrict__ wh, const __nv_bfloat16* __restrict__ wl,
    const float* __restrict__ bq, const float* __restrict__ bk,
    const float* __restrict__ bv,
    __half* __restrict__ q16, __half* __restrict__ k16, float* __restrict__ v)
{
    extern __shared__ char sm[];
    const int SBIAS = 55296;
    const int z = blockIdx.z;
    const int n0 = blockIdx.x * 64, m0 = blockIdx.y * 128;
    const int tid = threadIdx.x, lane = tid & 31, wid = tid >> 5;
    const int wm = wid >> 1, wn = wid & 1;
    const int qr = lane >> 2, qc = lane & 3;
    const float* bias = (z == 0) ? bq : (z == 1) ? bk : bv;

    if (tid < 16)
        *reinterpret_cast<float4*>(sm + SBIAS + tid * 16) =
            *reinterpret_cast<const float4*>(bias + n0 + tid * 4);

    float acc[2][4][4] = {};
    const int WN = Gg * Gg;
    gemm_mainloop(sm, xh + (size_t)z * NSG, xl + (size_t)z * NSG,
                  wh + (size_t)z * WN, wl + (size_t)z * WN, m0, n0, acc);

    const float* bs = reinterpret_cast<const float*>(sm + SBIAS);
    if (z < 2) {
        __half* C16 = (z == 0) ? q16 : k16;
        __half* sh = reinterpret_cast<__half*>(sm);             // stride 72
        #pragma unroll
        for (int mt = 0; mt < 2; mt++) {
            const int r0 = wm * 32 + mt * 16 + qr;
            #pragma unroll
            for (int nt = 0; nt < 4; nt++) {
                const int col = wn * 32 + nt * 8 + qc * 2;
                #pragma unroll
                for (int pr = 0; pr < 2; pr++) {
                    __half2 h2 = __floats2half2_rn(acc[mt][nt][pr * 2]     + bs[col],
                                                   acc[mt][nt][pr * 2 + 1] + bs[col + 1]);
                    *reinterpret_cast<__half2*>(sh + (r0 + pr * 8) * 72 + col) = h2;
                }
            }
        }
        __syncthreads();
        #pragma unroll
        for (int ps = 0; ps < 4; ps++) {
            const int idx = ps * 2048 + tid * 8;
            const int row = idx >> 6, col = idx & 63;
            uint4 hv = *reinterpret_cast<const uint4*>(sh + row * 72 + col);
            *reinterpret_cast<uint4*>(C16 + (size_t)(m0 + row) * Gg + n0 + col) = hv;
        }
    } else {
        float* sc = reinterpret_cast<float*>(sm);                // stride 68
        #pragma unroll
        for (int mt = 0; mt < 2; mt++) {
            const int r0 = wm * 32 + mt * 16 + qr;
            #pragma unroll
            for (int nt = 0; nt < 4; nt++) {
                const int col = wn * 32 + nt * 8 + qc * 2;
                #pragma unroll
                for (int pr = 0; pr < 2; pr++) {
                    float2 o = make_float2(acc[mt][nt][pr * 2]     + bs[col],
                                           acc[mt][nt][pr * 2 + 1] + bs[col + 1]);
                    *reinterpret_cast<float2*>(sc + (r0 + pr * 8) * 68 + col) = o;
                }
            }
        }
        __syncthreads();
        #pragma unroll
        for (int ps = 0; ps < 8; ps++) {
            const int idx = ps * 1024 + tid * 4;
            const int row = idx >> 6, col = idx & 63;
            float4 vv = *reinterpret_cast<const float4*>(sc + row * 68 + col);
            *reinterpret_cast<float4*>(v + (size_t)(m0 + row) * Gg + n0 + col) = vv;
        }
    }
}

// Out-projection (fp32 out).  grid (4, 64), 256 thr, smem 55552 B.
__global__ __launch_bounds__(256) void gemm_out_kernel(
    const __nv_bfloat16* __restrict__ Ahi, const __nv_bfloat16* __restrict__ Alo,
    const __nv_bfloat16* __restrict__ Whi, const __nv_bfloat16* __restrict__ Wlo,
    const float* __restrict__ bias, float* __restrict__ C)
{
    extern __shared__ char sm[];
    const int SBIAS = 55296;
    const int n0 = blockIdx.x * 64, m0 = blockIdx.y * 128;
    const int tid = threadIdx.x, lane = tid & 31, wid = tid >> 5;
    const int wm = wid >> 1, wn = wid & 1;
    const int qr = lane >> 2, qc = lane & 3;

    if (tid < 16)
        *reinterpret_cast<float4*>(sm + SBIAS + tid * 16) =
            *reinterpret_cast<const float4*>(bias + n0 + tid * 4);

    float acc[2][4][4] = {};
    gemm_mainloop(sm, Ahi, Alo, Whi, Wlo, m0, n0, acc);

    const float* bs = reinterpret_cast<const float*>(sm + SBIAS);
    float* sc = reinterpret_cast<float*>(sm);
    #pragma unroll
    for (int mt = 0; mt < 2; mt++) {
        const int r0 = wm * 32 + mt * 16 + qr;
        #pragma unroll
        for (int nt = 0; nt < 4; nt++) {
            const int col = wn * 32 + nt * 8 + qc * 2;
            #pragma unroll
            for (int pr = 0; pr < 2; pr++) {
                float2 o = make_float2(acc[mt][nt][pr * 2]     + bs[col],
                                       acc[mt][nt][pr * 2 + 1] + bs[col + 1]);
                *reinterpret_cast<float2*>(sc + (r0 + pr * 8) * 68 + col) = o;
            }
        }
    }
    __syncthreads();
    #pragma unroll
    for (int ps = 0; ps < 8; ps++) {
        const int idx = ps * 1024 + tid * 4;
        const int row = idx >> 6, col = idx & 63;
        float4 vv = *reinterpret_cast<const float4*>(sc + row * 68 + col);
        *reinterpret_cast<float4*>(C + (size_t)(m0 + row) * Gg + n0 + col) = vv;
    }
}

// ---------------------------------------------------------------------------
// scores: P(fp16) = exp(scale*QK^T), single-pass fp16 MMA.  (unchanged R8)
// ---------------------------------------------------------------------------
__global__ __launch_bounds__(256) void scores_wm_kernel(
    const __half* __restrict__ Q, const __half* __restrict__ Kt,
    __half* __restrict__ P, float* __restrict__ part)
{
    extern __shared__ char sm[];
    const int QH = 0, KH = 18432, STG_BASE = 36864;
    const int tid = threadIdx.x, lane = tid & 31, wid = tid >> 5;
    const int wm = wid >> 2, wn = wid & 3;
    const int bh = blockIdx.z, b = bh >> 2, h = bh & 3;
    const int i0 = blockIdx.y * 128, j0 = blockIdx.x * 128;

    {
        const int row = tid >> 1, half = tid & 1;
        const size_t qoff = ((size_t)(b * Ss + i0 + row)) * Gg + h * DKk + half * 32;
        const size_t koff = ((size_t)(b * Ss + j0 + row)) * Gg + h * DKk + half * 32;
        const unsigned so = row * 144 + half * 64;
        const uint4* q1 = reinterpret_cast<const uint4*>(Q + qoff);
        const uint4* k1 = reinterpret_cast<const uint4*>(Kt + koff);
        #pragma unroll
        for (int u = 0; u < 4; u++) {
            *reinterpret_cast<uint4*>(sm + QH + so + u * 16) = q1[u];
            *reinterpret_cast<uint4*>(sm + KH + so + u * 16) = k1[u];
        }
    }
    __syncthreads();

    const unsigned base = smem_u32(sm);
    const int qr = lane >> 2, qc = lane & 3;
    const unsigned aoff = (wm * 64 + (lane & 15)) * 144 + ((lane >> 4) * 8) * 2;
    const unsigned boff = (wn * 32 + ((lane >> 4) & 1) * 8 + (lane & 7)) * 144
                        + (((lane >> 3) & 1) * 8) * 2;

    float acc[4][4][4] = {};
    #pragma unroll
    for (int kk = 0; kk < 4; kk++) {
        unsigned aH[4][4], bH[2][4];
        #pragma unroll
        for (int mt = 0; mt < 4; mt++) {
            const unsigned ad = base + QH + aoff + mt * 2304 + kk * 32;
            ldsm4(aH[mt][0], aH[mt][1], aH[mt][2], aH[mt][3], ad);
        }
        #pragma unroll
        for (int g = 0; g < 2; g++) {
            const unsigned bd = base + KH + boff + g * 2304 + kk * 32;
            ldsm4(bH[g][0], bH[g][1], bH[g][2], bH[g][3], bd);
        }
        #pragma unroll
        for (int mt = 0; mt < 4; mt++)
            #pragma unroll
            for (int nt = 0; nt < 4; nt++)
                mma_f16(acc[mt][nt], aH[mt], &bH[nt >> 1][(nt & 1) * 2]);
    }

    #pragma unroll
    for (int mt = 0; mt < 4; mt++)
        #pragma unroll
        for (int nt = 0; nt < 4; nt++)
            #pragma unroll
            for (int r = 0; r < 4; r++)
                acc[mt][nt][r] = ex2f(acc[mt][nt][r] * EXP2K);

    const int jbase = j0 + wn * 32;
    #pragma unroll
    for (int nt = 0; nt < 4; nt++) {
        #pragma unroll
        for (int p = 0; p < 2; p++) {
            float s = 0.f;
            #pragma unroll
            for (int mt = 0; mt < 4; mt++) s += acc[mt][nt][p] + acc[mt][nt][p + 2];
            #pragma unroll
            for (int o = 4; o < 32; o <<= 1) s += __shfl_xor_sync(0xffffffffu, s, o);
            if (qr == 0)
                part[((size_t)(bh * 32 + blockIdx.y) * 2 + wm) * Ss
                     + jbase + nt * 8 + qc * 2 + p] = s;
        }
    }

    __syncthreads();
    __half* stg = reinterpret_cast<__half*>(sm + STG_BASE);
    #pragma unroll
    for (int mt = 0; mt < 4; mt++) {
        const int r0 = wm * 64 + mt * 16 + qr;
        #pragma unroll
        for (int nt = 0; nt < 4; nt++) {
            const int col = wn * 32 + nt * 8 + qc * 2;
            #pragma unroll
            for (int pr = 0; pr < 2; pr++) {
                __half2 h2 = __floats2half2_rn(acc[mt][nt][pr * 2],
                                               acc[mt][nt][pr * 2 + 1]);
                *reinterpret_cast<__half2*>(stg + (r0 + pr * 8) * 136 + col) = h2;
            }
        }
    }
    __syncthreads();
    {
        const size_t pb = ((size_t)bh * Ss + i0) * Ss + j0;
        #pragma unroll
        for (int ps = 0; ps < 8; ps++) {
            const int el = ps * 2048 + tid * 8;
            const int row = el >> 7, col = el & 127;
            uint4 vv = *reinterpret_cast<const uint4*>(stg + row * 136 + col);
            *reinterpret_cast<uint4*>(P + pb + (size_t)row * Ss + col) = vv;
        }
    }
}

// winv[bh,j] = 1/sum_{c<64} part[bh*64+c, j].  grid (16,8) x 256
__global__ __launch_bounds__(256) void colsum_final_kernel(
    const float* __restrict__ part, float* __restrict__ winv)
{
    const int j = blockIdx.x * 256 + threadIdx.x;
    const int bh = blockIdx.y;
    const float* p = part + (size_t)bh * 64 * Ss + j;
    float s = 0.f;
    #pragma unroll 8
    for (int c = 0; c < 64; c++) s += p[(size_t)c * Ss];
    winv[(size_t)bh * Ss + j] = 1.0f / s;
}

// vT[bh,d,j] = v[b,j,h*64+d]*winv[bh,j]*4096 -> fp16.  grid (64,8) x 256
__global__ __launch_bounds__(256) void scale_v_t_kernel(
    const float* __restrict__ v, const float* __restrict__ winv,
    __half* __restrict__ tH)
{
    __shared__ float ts[64][65];
    const int tid = threadIdx.x, bh = blockIdx.y, b = bh >> 2, h = bh & 3;
    const int j0 = blockIdx.x * 64;
    {
        const int j = tid >> 2, c0 = (tid & 3) * 16;
        const float* src = v + ((size_t)(b * Ss + j0 + j)) * Gg + h * DKk + c0;
        #pragma unroll
        for (int u = 0; u < 4; u++) {
            float4 f = *reinterpret_cast<const float4*>(src + u * 4);
            ts[j][c0 + 4*u]     = f.x; ts[j][c0 + 4*u + 1] = f.y;
            ts[j][c0 + 4*u + 2] = f.z; ts[j][c0 + 4*u + 3] = f.w;
        }
    }
    __syncthreads();
    const int d = tid >> 2, jj0 = (tid & 3) * 16;
    const size_t ob = (((size_t)bh) * DKk + d) * Ss + j0 + jj0;
    const float* wv = winv + (size_t)bh * Ss + j0 + jj0;
    __half hbuf[16];
    #pragma unroll
    for (int u = 0; u < 16; u++)
        hbuf[u] = __float2half_rn(ts[jj0 + u][d] * wv[u] * VSCALE);
    #pragma unroll
    for (int u = 0; u < 2; u++)
        *reinterpret_cast<uint4*>(tH + ob + u * 8) = reinterpret_cast<uint4*>(hbuf)[u];
}

// ---------------------------------------------------------------------------
// pv: Att = (P @ Vw^T)/4096, single fp16 MMA pass.  CTA 128x64, K=4096.
// 8 warps 4(m) x 2(n).  grid (32,8), 256 thr, smem 27648 B.
// ---------------------------------------------------------------------------
__global__ __launch_bounds__(256) void pv_wm_kernel(
    const __half* __restrict__ P, const __half* __restrict__ vt,
    float* __restrict__ att)
{
    extern __shared__ char sm[];
    const int PH = 0, VH = 18432;
    const int tid = threadIdx.x, lane = tid & 31, wid = tid >> 5;
    const int wm = wid >> 1, wn = wid & 1;
    const int bh = blockIdx.y, b = bh >> 2, h = bh & 3;
    const int i0 = blockIdx.x * 128;
    const int qr = lane >> 2, qc = lane & 3;

    const int prow = tid >> 1, phalf = tid & 1;
    const __half* pS = P + ((size_t)bh * Ss + i0 + prow) * Ss + phalf * 32;
    const unsigned pso = prow * 144 + phalf * 64;
    const int vrow = tid >> 2, vq = tid & 3;
    const __half* vS = vt + ((size_t)bh * DKk + vrow) * Ss + vq * 16;
    const unsigned vso = VH + vrow * 144 + vq * 32;

    const unsigned base = smem_u32(sm);
    const unsigned aoff = (wm * 32 + (lane & 15)) * 144 + ((lane >> 4) * 8) * 2;
    const unsigned boff = (wn * 32 + ((lane >> 4) & 1) * 8 + (lane & 7)) * 144
                        + (((lane >> 3) & 1) * 8) * 2;

    float acc[2][4][4] = {};
    uint4 rp[4], rv[2];

    #pragma unroll
    for (int u = 0; u < 4; u++) rp[u] = reinterpret_cast<const uint4*>(pS)[u];
    rv[0] = reinterpret_cast<const uint4*>(vS)[0];
    rv[1] = reinterpret_cast<const uint4*>(vS)[1];

    for (int c = 0; c < 64; c++) {
        #pragma unroll
        for (int u = 0; u < 4; u++)
            *reinterpret_cast<uint4*>(sm + PH + pso + u * 16) = rp[u];
        *reinterpret_cast<uint4*>(sm + vso)      = rv[0];
        *reinterpret_cast<uint4*>(sm + vso + 16) = rv[1];
        __syncthreads();

        if (c < 63) {
            const size_t go = (size_t)(c + 1) * 64;
            #pragma unroll
            for (int u = 0; u < 4; u++)
                rp[u] = reinterpret_cast<const uint4*>(pS + go)[u];
            rv[0] = reinterpret_cast<const uint4*>(vS + go)[0];
            rv[1] = reinterpret_cast<const uint4*>(vS + go)[1];
        }

        #pragma unroll
        for (int kk = 0; kk < 4; kk++) {
            unsigned aH[2][4], bH[2][4];
            #pragma unroll
            for (int mt = 0; mt < 2; mt++) {
                const unsigned ad = base + PH + aoff + mt * 2304 + kk * 32;
                ldsm4(aH[mt][0], aH[mt][1], aH[mt][2], aH[mt][3], ad);
            }
            #pragma unroll
            for (int g = 0; g < 2; g++) {
                const unsigned bd = base + VH + boff + g * 2304 + kk * 32;
                ldsm4(bH[g][0], bH[g][1], bH[g][2], bH[g][3], bd);
            }
            #pragma unroll
            for (int mt = 0; mt < 2; mt++)
                #pragma unroll
                for (int nt = 0; nt < 4; nt++)
                    mma_f16(acc[mt][nt], aH[mt], &bH[nt >> 1][(nt & 1) * 2]);
        }
        __syncthreads();
    }

    #pragma unroll
    for (int mt = 0; mt < 2; mt++) {
        const int row0 = i0 + wm * 32 + mt * 16 + qr;
        #pragma unroll
        for (int nt = 0; nt < 4; nt++) {
            const int col = h * DKk + wn * 32 + nt * 8 + qc * 2;
            #pragma unroll
            for (int pr = 0; pr < 2; pr++) {
                float2 o = make_float2(acc[mt][nt][pr * 2] * OSCALE,
                                       acc[mt][nt][pr * 2 + 1] * OSCALE);
                *reinterpret_cast<float2*>(
                    att + ((size_t)(b * Ss + row0 + pr * 8)) * Gg + col) = o;
            }
        }
    }
}

// ---------------------------------------------------------------------------
extern "C" void kernel_launch(void* const* d_in, const int* in_sizes, int n_in,
                              void* d_out, int out_size)
{
    const float* x  = (const float*)d_in[0];
    const float* wq = (const float*)d_in[1];
    const float* bq = (const float*)d_in[2];
    const float* wk = (const float*)d_in[3];
    const float* bk = (const float*)d_in[4];
    const float* wv = (const float*)d_in[5];
    const float* bv = (const float*)d_in[6];
    const float* wo = (const float*)d_in[7];
    const float* bo = (const float*)d_in[8];
    float* out = (float*)d_out;

    __nv_bfloat16 *xh, *xl, *wh, *wl, *atth, *attl;
    __half *q16, *k16, *p, *vt;
    float *v, *part, *winv, *att;
    cudaGetSymbolAddress((void**)&xh,  g_xh);   cudaGetSymbolAddress((void**)&xl,  g_xl);
    cudaGetSymbolAddress((void**)&wh,  g_wh);   cudaGetSymbolAddress((void**)&wl,  g_wl);
    cudaGetSymbolAddress((void**)&q16, g_q16);  cudaGetSymbolAddress((void**)&k16, g_k16);
    cudaGetSymbolAddress((void**)&v,   g_v);
    cudaGetSymbolAddress((void**)&p,   g_p);
    cudaGetSymbolAddress((void**)&part,g_part); cudaGetSymbolAddress((void**)&winv,g_winv);
    cudaGetSymbolAddress((void**)&vt,  g_vt);
    cudaGetSymbolAddress((void**)&att, g_att);
    cudaGetSymbolAddress((void**)&atth,g_atth); cudaGetSymbolAddress((void**)&attl,g_attl);

    const int SC_SMEM = 71680;
    const int PV_SMEM = 27648;
    const int TC_SMEM = 55552;
    cudaFuncSetAttribute(scores_wm_kernel, cudaFuncAttributeMaxDynamicSharedMemorySize, SC_SMEM);
    cudaFuncSetAttribute(pv_wm_kernel,     cudaFuncAttributeMaxDynamicSharedMemorySize, PV_SMEM);
    cudaFuncSetAttribute(gemm_qkv_kernel,  cudaFuncAttributeMaxDynamicSharedMemorySize, TC_SMEM);
    cudaFuncSetAttribute(gemm_out_kernel,  cudaFuncAttributeMaxDynamicSharedMemorySize, TC_SMEM);

    const int WN = Gg * Gg;

    // splits
    split_x_kernel<<<6144, 256>>>(x, xh, xl);
    split1_kernel<<<64, 256>>>(wq, wh + 0 * WN, wl + 0 * WN, WN / 4);
    split1_kernel<<<64, 256>>>(wk, wh + 1 * WN, wl + 1 * WN, WN / 4);
    split1_kernel<<<64, 256>>>(wv, wh + 2 * WN, wl + 2 * WN, WN / 4);
    split1_kernel<<<64, 256>>>(wo, wh + 3 * WN, wl + 3 * WN, WN / 4);

    // QKV projections: one batched launch
    gemm_qkv_kernel<<<dim3(4, 64, 3), 256, TC_SMEM>>>(
        xh, xl, wh, wl, bq, bk, bv, q16, k16, v);

    // attention
    scores_wm_kernel<<<dim3(32, 32, 8), 256, SC_SMEM>>>(q16, k16, p, part);
    colsum_final_kernel<<<dim3(16, 8), 256>>>(part, winv);
    scale_v_t_kernel<<<dim3(64, 8), 256>>>(v, winv, vt);
    pv_wm_kernel<<<dim3(32, 8), 256, PV_SMEM>>>(p, vt, att);

    // out projection
    split1_kernel<<<2048, 256>>>(att, atth, attl, NSG / 4);
    gemm_out_kernel<<<dim3(4, 64), 256, TC_SMEM>>>(atth, attl,
        wh + 3 * WN, wl + 3 * WN, bo, out);
}

// round 10
// speedup vs baseline: 3.8064x; 1.0472x over previous
#include <cuda_runtime.h>
#include <cuda_bf16.h>
#include <cuda_fp16.h>
#include <math.h>

#define Bb   2
#define Ss   4096
#define Gg   256
#define Hh   4
#define DKk  64
#define DIMd 768
#define EXP2K (0.125f * 1.44269504088896341f)
#define VSCALE 4096.0f
#define OSCALE (1.0f / 4096.0f)
#define NSG (Bb * Ss * Gg)

// ---------------- scratch ----------------
__device__ __nv_bfloat16 g_xh[3 * NSG];
__device__ __nv_bfloat16 g_xl[3 * NSG];
__device__ __nv_bfloat16 g_wh[4 * Gg * Gg];
__device__ __nv_bfloat16 g_wl[4 * Gg * Gg];
__device__ __half g_q16[NSG];
__device__ __half g_k16[NSG];
__device__ float  g_v  [NSG];
__device__ __half g_p[(size_t)Bb * Hh * Ss * Ss];            // 268 MB
__device__ float g_part[(size_t)Bb * Hh * 64 * Ss];
__device__ __half g_vt[Bb * Hh * DKk * Ss];                  // (V^T*winv*4096) fp16
__device__ __nv_bfloat16 g_atth[NSG];
__device__ __nv_bfloat16 g_attl[NSG];

// ---------------- helpers ----------------
__device__ __forceinline__ unsigned smem_u32(const void* p) {
    unsigned a;
    asm("{ .reg .u64 t; cvta.to.shared.u64 t, %1; cvt.u32.u64 %0, t; }" : "=r"(a) : "l"(p));
    return a;
}
__device__ __forceinline__ float ex2f(float x) {
    float r;
    asm("ex2.approx.ftz.f32 %0, %1;" : "=f"(r) : "f"(x));
    return r;
}
__device__ __forceinline__ void ldsm4(unsigned& r0, unsigned& r1, unsigned& r2,
                                      unsigned& r3, unsigned addr) {
    asm volatile("ldmatrix.sync.aligned.m8n8.x4.shared.b16 {%0,%1,%2,%3}, [%4];"
                 : "=r"(r0), "=r"(r1), "=r"(r2), "=r"(r3) : "r"(addr));
}
__device__ __forceinline__ void mma_bf16(float* c, const unsigned* a, const unsigned* b) {
    asm volatile(
        "mma.sync.aligned.m16n8k16.row.col.f32.bf16.bf16.f32 "
        "{%0,%1,%2,%3},{%4,%5,%6,%7},{%8,%9},{%0,%1,%2,%3};"
        : "+f"(c[0]), "+f"(c[1]), "+f"(c[2]), "+f"(c[3])
        : "r"(a[0]), "r"(a[1]), "r"(a[2]), "r"(a[3]), "r"(b[0]), "r"(b[1]));
}
__device__ __forceinline__ void mma_f16(float* c, const unsigned* a, const unsigned* b) {
    asm volatile(
        "mma.sync.aligned.m16n8k16.row.col.f32.f16.f16.f32 "
        "{%0,%1,%2,%3},{%4,%5,%6,%7},{%8,%9},{%0,%1,%2,%3};"
        : "+f"(c[0]), "+f"(c[1]), "+f"(c[2]), "+f"(c[3])
        : "r"(a[0]), "r"(a[1]), "r"(a[2]), "r"(a[3]), "r"(b[0]), "r"(b[1]));
}
__device__ __forceinline__ void split2(float a, float b, unsigned& h, unsigned& l) {
    __nv_bfloat162 h2 = __floats2bfloat162_rn(a, b);
    __nv_bfloat162 l2 = __floats2bfloat162_rn(a - __bfloat162float(h2.x),
                                              b - __bfloat162float(h2.y));
    h = *reinterpret_cast<unsigned*>(&h2);
    l = *reinterpret_cast<unsigned*>(&l2);
}

// ---------------- split kernels ----------------
__global__ __launch_bounds__(256) void split_x_kernel(
    const float* __restrict__ x, __nv_bfloat16* __restrict__ hi,
    __nv_bfloat16* __restrict__ lo)
{
    const int i = blockIdx.x * 256 + threadIdx.x;
    float4 f = reinterpret_cast<const float4*>(x)[i];
    const int row = i / 192, c4 = i - row * 192;
    const int slice = c4 >> 6, w4 = c4 & 63;
    const size_t o = (size_t)slice * NSG + (size_t)row * Gg + w4 * 4;
    uint2 hv, lv;
    split2(f.x, f.y, hv.x, lv.x);
    split2(f.z, f.w, hv.y, lv.y);
    *reinterpret_cast<uint2*>(hi + o) = hv;
    *reinterpret_cast<uint2*>(lo + o) = lv;
}

// all 4 weight splits in one launch: grid (64, 4)
__global__ __launch_bounds__(256) void split_w_kernel(
    const float* __restrict__ w0, const float* __restrict__ w1,
    const float* __restrict__ w2, const float* __restrict__ w3,
    __nv_bfloat16* __restrict__ hi, __nv_bfloat16* __restrict__ lo)
{
    const int z = blockIdx.y;
    const float* src = (z == 0) ? w0 : (z == 1) ? w1 : (z == 2) ? w2 : w3;
    const int i = blockIdx.x * 256 + threadIdx.x;       // float4 index
    float4 f = reinterpret_cast<const float4*>(src)[i];
    uint2 hv, lv;
    split2(f.x, f.y, hv.x, lv.x);
    split2(f.z, f.w, hv.y, lv.y);
    const size_t o = (size_t)z * Gg * Gg + (size_t)i * 4;
    *reinterpret_cast<uint2*>(hi + o) = hv;
    *reinterpret_cast<uint2*>(lo + o) = lv;
}

// ---------------------------------------------------------------------------
// Shared bf16x3 GEMM mainloop: acc += A[M,256] @ W[256,256]^T, 128x64 tile.
// ---------------------------------------------------------------------------
__device__ __forceinline__ void gemm_mainloop(
    char* sm, const __nv_bfloat16* Ahi, const __nv_bfloat16* Alo,
    const __nv_bfloat16* Whi, const __nv_bfloat16* Wlo,
    int m0, int n0, float acc[2][4][4])
{
    const int AH = 0, AL = 18432, WH = 36864, WL = 46080;
    const int tid = threadIdx.x, lane = tid & 31, wid = tid >> 5;
    const int wm = wid >> 1, wn = wid & 1;

    const int arow = tid >> 1, ahalf = tid & 1;
    const __nv_bfloat16* aH = Ahi + (size_t)(m0 + arow) * Gg + ahalf * 32;
    const __nv_bfloat16* aL = Alo + (size_t)(m0 + arow) * Gg + ahalf * 32;
    const unsigned aso = arow * 144 + ahalf * 64;
    const int wrow = tid >> 2, wq = tid & 3;
    const __nv_bfloat16* wH = Whi + (size_t)(n0 + wrow) * Gg + wq * 16;
    const __nv_bfloat16* wL = Wlo + (size_t)(n0 + wrow) * Gg + wq * 16;
    const unsigned wso = wrow * 144 + wq * 32;

    const unsigned base = smem_u32(sm);
    const unsigned aoff = (wm * 32 + (lane & 15)) * 144 + ((lane >> 4) * 8) * 2;
    const unsigned boff = (wn * 32 + ((lane >> 4) & 1) * 8 + (lane & 7)) * 144
                        + (((lane >> 3) & 1) * 8) * 2;

    uint4 rah[4], ral[4], rwh[2], rwl[2];
    #pragma unroll
    for (int u = 0; u < 4; u++) {
        rah[u] = reinterpret_cast<const uint4*>(aH)[u];
        ral[u] = reinterpret_cast<const uint4*>(aL)[u];
    }
    #pragma unroll
    for (int u = 0; u < 2; u++) {
        rwh[u] = reinterpret_cast<const uint4*>(wH)[u];
        rwl[u] = reinterpret_cast<const uint4*>(wL)[u];
    }

    for (int c = 0; c < 4; c++) {
        #pragma unroll
        for (int u = 0; u < 4; u++) {
            *reinterpret_cast<uint4*>(sm + AH + aso + u * 16) = rah[u];
            *reinterpret_cast<uint4*>(sm + AL + aso + u * 16) = ral[u];
        }
        #pragma unroll
        for (int u = 0; u < 2; u++) {
            *reinterpret_cast<uint4*>(sm + WH + wso + u * 16) = rwh[u];
            *reinterpret_cast<uint4*>(sm + WL + wso + u * 16) = rwl[u];
        }
        __syncthreads();

        if (c < 3) {
            const int go = (c + 1) * 64;
            #pragma unroll
            for (int u = 0; u < 4; u++) {
                rah[u] = reinterpret_cast<const uint4*>(aH + go)[u];
                ral[u] = reinterpret_cast<const uint4*>(aL + go)[u];
            }
            #pragma unroll
            for (int u = 0; u < 2; u++) {
                rwh[u] = reinterpret_cast<const uint4*>(wH + go)[u];
                rwl[u] = reinterpret_cast<const uint4*>(wL + go)[u];
            }
        }

        #pragma unroll
        for (int kk = 0; kk < 4; kk++) {
            unsigned fah[2][4], fal[2][4], fbh[2][4], fbl[2][4];
            #pragma unroll
            for (int mt = 0; mt < 2; mt++) {
                const unsigned ad = base + AH + aoff + mt * 2304 + kk * 32;
                ldsm4(fah[mt][0], fah[mt][1], fah[mt][2], fah[mt][3], ad);
                ldsm4(fal[mt][0], fal[mt][1], fal[mt][2], fal[mt][3], ad + (AL - AH));
            }
            #pragma unroll
            for (int g = 0; g < 2; g++) {
                const unsigned bd = base + WH + boff + g * 2304 + kk * 32;
                ldsm4(fbh[g][0], fbh[g][1], fbh[g][2], fbh[g][3], bd);
                ldsm4(fbl[g][0], fbl[g][1], fbl[g][2], fbl[g][3], bd + (WL - WH));
            }
            #pragma unroll
            for (int mt = 0; mt < 2; mt++)
                #pragma unroll
                for (int nt = 0; nt < 4; nt++) {
                    const unsigned* pbh = &fbh[nt >> 1][(nt & 1) * 2];
                    const unsigned* pbl = &fbl[nt >> 1][(nt & 1) * 2];
                    mma_bf16(acc[mt][nt], fah[mt], pbh);
                    mma_bf16(acc[mt][nt], fah[mt], pbl);
                    mma_bf16(acc[mt][nt], fal[mt], pbh);
                }
        }
        __syncthreads();
    }
}

// Batched QKV projection: blockIdx.z = 0(Q,fp16), 1(K,fp16), 2(V,fp32).
__global__ __launch_bounds__(256) void gemm_qkv_kernel(
    const __nv_bfloat16* __restrict__ xh, const __nv_bfloat16* __restrict__ xl,
    const __nv_bfloat16* __restrict__ wh, const __nv_bfloat16* __restrict__ wl,
    const float* __restrict__ bq, const float* __restrict__ bk,
    const float* __restrict__ bv,
    __half* __restrict__ q16, __half* __restrict__ k16, float* __restrict__ v)
{
    extern __shared__ char sm[];
    const int SBIAS = 55296;
    const int z = blockIdx.z;
    const int n0 = blockIdx.x * 64, m0 = blockIdx.y * 128;
    const int tid = threadIdx.x, lane = tid & 31, wid = tid >> 5;
    const int wm = wid >> 1, wn = wid & 1;
    const int qr = lane >> 2, qc = lane & 3;
    const float* bias = (z == 0) ? bq : (z == 1) ? bk : bv;

    if (tid < 16)
        *reinterpret_cast<float4*>(sm + SBIAS + tid * 16) =
            *reinterpret_cast<const float4*>(bias + n0 + tid * 4);

    float acc[2][4][4] = {};
    const int WN = Gg * Gg;
    gemm_mainloop(sm, xh + (size_t)z * NSG, xl + (size_t)z * NSG,
                  wh + (size_t)z * WN, wl + (size_t)z * WN, m0, n0, acc);

    const float* bs = reinterpret_cast<const float*>(sm + SBIAS);
    if (z < 2) {
        __half* C16 = (z == 0) ? q16 : k16;
        __half* sh = reinterpret_cast<__half*>(sm);             // stride 72
        #pragma unroll
        for (int mt = 0; mt < 2; mt++) {
            const int r0 = wm * 32 + mt * 16 + qr;
            #pragma unroll
            for (int nt = 0; nt < 4; nt++) {
                const int col = wn * 32 + nt * 8 + qc * 2;
                #pragma unroll
                for (int pr = 0; pr < 2; pr++) {
                    __half2 h2 = __floats2half2_rn(acc[mt][nt][pr * 2]     + bs[col],
                                                   acc[mt][nt][pr * 2 + 1] + bs[col + 1]);
                    *reinterpret_cast<__half2*>(sh + (r0 + pr * 8) * 72 + col) = h2;
                }
            }
        }
        __syncthreads();
        #pragma unroll
        for (int ps = 0; ps < 4; ps++) {
            const int idx = ps * 2048 + tid * 8;
            const int row = idx >> 6, col = idx & 63;
            uint4 hv = *reinterpret_cast<const uint4*>(sh + row * 72 + col);
            *reinterpret_cast<uint4*>(C16 + (size_t)(m0 + row) * Gg + n0 + col) = hv;
        }
    } else {
        float* sc = reinterpret_cast<float*>(sm);                // stride 68
        #pragma unroll
        for (int mt = 0; mt < 2; mt++) {
            const int r0 = wm * 32 + mt * 16 + qr;
            #pragma unroll
            for (int nt = 0; nt < 4; nt++) {
                const int col = wn * 32 + nt * 8 + qc * 2;
                #pragma unroll
                for (int pr = 0; pr < 2; pr++) {
                    float2 o = make_float2(acc[mt][nt][pr * 2]     + bs[col],
                                           acc[mt][nt][pr * 2 + 1] + bs[col + 1]);
                    *reinterpret_cast<float2*>(sc + (r0 + pr * 8) * 68 + col) = o;
                }
            }
        }
        __syncthreads();
        #pragma unroll
        for (int ps = 0; ps < 8; ps++) {
            const int idx = ps * 1024 + tid * 4;
            const int row = idx >> 6, col = idx & 63;
            float4 vv = *reinterpret_cast<const float4*>(sc + row * 68 + col);
            *reinterpret_cast<float4*>(v + (size_t)(m0 + row) * Gg + n0 + col) = vv;
        }
    }
}

// Out-projection (fp32 out).
__global__ __launch_bounds__(256) void gemm_out_kernel(
    const __nv_bfloat16* __restrict__ Ahi, const __nv_bfloat16* __restrict__ Alo,
    const __nv_bfloat16* __restrict__ Whi, const __nv_bfloat16* __restrict__ Wlo,
    const float* __restrict__ bias, float* __restrict__ C)
{
    extern __shared__ char sm[];
    const int SBIAS = 55296;
    const int n0 = blockIdx.x * 64, m0 = blockIdx.y * 128;
    const int tid = threadIdx.x, lane = tid & 31, wid = tid >> 5;
    const int wm = wid >> 1, wn = wid & 1;
    const int qr = lane >> 2, qc = lane & 3;

    if (tid < 16)
        *reinterpret_cast<float4*>(sm + SBIAS + tid * 16) =
            *reinterpret_cast<const float4*>(bias + n0 + tid * 4);

    float acc[2][4][4] = {};
    gemm_mainloop(sm, Ahi, Alo, Whi, Wlo, m0, n0, acc);

    const float* bs = reinterpret_cast<const float*>(sm + SBIAS);
    float* sc = reinterpret_cast<float*>(sm);
    #pragma unroll
    for (int mt = 0; mt < 2; mt++) {
        const int r0 = wm * 32 + mt * 16 + qr;
        #pragma unroll
        for (int nt = 0; nt < 4; nt++) {
            const int col = wn * 32 + nt * 8 + qc * 2;
            #pragma unroll
            for (int pr = 0; pr < 2; pr++) {
                float2 o = make_float2(acc[mt][nt][pr * 2]     + bs[col],
                                       acc[mt][nt][pr * 2 + 1] + bs[col + 1]);
                *reinterpret_cast<float2*>(sc + (r0 + pr * 8) * 68 + col) = o;
            }
        }
    }
    __syncthreads();
    #pragma unroll
    for (int ps = 0; ps < 8; ps++) {
        const int idx = ps * 1024 + tid * 4;
        const int row = idx >> 6, col = idx & 63;
        float4 vv = *reinterpret_cast<const float4*>(sc + row * 68 + col);
        *reinterpret_cast<float4*>(C + (size_t)(m0 + row) * Gg + n0 + col) = vv;
    }
}

// ---------------------------------------------------------------------------
// scores: P(fp16) = exp(scale*QK^T), single-pass fp16 MMA.  Staging reuses the
// Q/K smem region -> dyn smem 36864 B.  grid (32,32,8), 256 thr.
// ---------------------------------------------------------------------------
__global__ __launch_bounds__(256) void scores_wm_kernel(
    const __half* __restrict__ Q, const __half* __restrict__ Kt,
    __half* __restrict__ P, float* __restrict__ part)
{
    extern __shared__ char sm[];
    const int QH = 0, KH = 18432;
    const int tid = threadIdx.x, lane = tid & 31, wid = tid >> 5;
    const int wm = wid >> 2, wn = wid & 3;
    const int bh = blockIdx.z, b = bh >> 2, h = bh & 3;
    const int i0 = blockIdx.y * 128, j0 = blockIdx.x * 128;

    {
        const int row = tid >> 1, half = tid & 1;
        const size_t qoff = ((size_t)(b * Ss + i0 + row)) * Gg + h * DKk + half * 32;
        const size_t koff = ((size_t)(b * Ss + j0 + row)) * Gg + h * DKk + half * 32;
        const unsigned so = row * 144 + half * 64;
        const uint4* q1 = reinterpret_cast<const uint4*>(Q + qoff);
        const uint4* k1 = reinterpret_cast<const uint4*>(Kt + koff);
        #pragma unroll
        for (int u = 0; u < 4; u++) {
            *reinterpret_cast<uint4*>(sm + QH + so + u * 16) = q1[u];
            *reinterpret_cast<uint4*>(sm + KH + so + u * 16) = k1[u];
        }
    }
    __syncthreads();

    const unsigned base = smem_u32(sm);
    const int qr = lane >> 2, qc = lane & 3;
    const unsigned aoff = (wm * 64 + (lane & 15)) * 144 + ((lane >> 4) * 8) * 2;
    const unsigned boff = (wn * 32 + ((lane >> 4) & 1) * 8 + (lane & 7)) * 144
                        + (((lane >> 3) & 1) * 8) * 2;

    float acc[4][4][4] = {};
    #pragma unroll
    for (int kk = 0; kk < 4; kk++) {
        unsigned aH[4][4], bH[2][4];
        #pragma unroll
        for (int mt = 0; mt < 4; mt++) {
            const unsigned ad = base + QH + aoff + mt * 2304 + kk * 32;
            ldsm4(aH[mt][0], aH[mt][1], aH[mt][2], aH[mt][3], ad);
        }
        #pragma unroll
        for (int g = 0; g < 2; g++) {
            const unsigned bd = base + KH + boff + g * 2304 + kk * 32;
            ldsm4(bH[g][0], bH[g][1], bH[g][2], bH[g][3], bd);
        }
        #pragma unroll
        for (int mt = 0; mt < 4; mt++)
            #pragma unroll
            for (int nt = 0; nt < 4; nt++)
                mma_f16(acc[mt][nt], aH[mt], &bH[nt >> 1][(nt & 1) * 2]);
    }

    #pragma unroll
    for (int mt = 0; mt < 4; mt++)
        #pragma unroll
        for (int nt = 0; nt < 4; nt++)
            #pragma unroll
            for (int r = 0; r < 4; r++)
                acc[mt][nt][r] = ex2f(acc[mt][nt][r] * EXP2K);

    const int jbase = j0 + wn * 32;
    #pragma unroll
    for (int nt = 0; nt < 4; nt++) {
        #pragma unroll
        for (int p = 0; p < 2; p++) {
            float s = 0.f;
            #pragma unroll
            for (int mt = 0; mt < 4; mt++) s += acc[mt][nt][p] + acc[mt][nt][p + 2];
            #pragma unroll
            for (int o = 4; o < 32; o <<= 1) s += __shfl_xor_sync(0xffffffffu, s, o);
            if (qr == 0)
                part[((size_t)(bh * 32 + blockIdx.y) * 2 + wm) * Ss
                     + jbase + nt * 8 + qc * 2 + p] = s;
        }
    }

    __syncthreads();            // all LDSM reads done -> reuse Q/K region
    __half* stg = reinterpret_cast<__half*>(sm);
    #pragma unroll
    for (int mt = 0; mt < 4; mt++) {
        const int r0 = wm * 64 + mt * 16 + qr;
        #pragma unroll
        for (int nt = 0; nt < 4; nt++) {
            const int col = wn * 32 + nt * 8 + qc * 2;
            #pragma unroll
            for (int pr = 0; pr < 2; pr++) {
                __half2 h2 = __floats2half2_rn(acc[mt][nt][pr * 2],
                                               acc[mt][nt][pr * 2 + 1]);
                *reinterpret_cast<__half2*>(stg + (r0 + pr * 8) * 136 + col) = h2;
            }
        }
    }
    __syncthreads();
    {
        const size_t pb = ((size_t)bh * Ss + i0) * Ss + j0;
        #pragma unroll
        for (int ps = 0; ps < 8; ps++) {
            const int el = ps * 2048 + tid * 8;
            const int row = el >> 7, col = el & 127;
            uint4 vv = *reinterpret_cast<const uint4*>(stg + row * 136 + col);
            *reinterpret_cast<uint4*>(P + pb + (size_t)row * Ss + col) = vv;
        }
    }
}

// ---------------------------------------------------------------------------
// Fused colsum + V scale/transpose: winv[j] = 1/sum_c part[bh,c,j] computed
// in-CTA, then vT[bh,d,j] = v[b,j,h*64+d]*winv[j]*4096 -> fp16.
// grid (64,8) x 256
// ---------------------------------------------------------------------------
__global__ __launch_bounds__(256) void scale_v_t_kernel(
    const float* __restrict__ v, const float* __restrict__ part,
    __half* __restrict__ tH)
{
    __shared__ float ts[64][65];
    __shared__ float wsum[4][64];
    __shared__ float winv_s[64];
    const int tid = threadIdx.x, bh = blockIdx.y, b = bh >> 2, h = bh & 3;
    const int j0 = blockIdx.x * 64;

    {   // column-sum over 64 partials (deterministic fixed order)
        const int j = tid & 63, cq = tid >> 6;      // cq in 0..3
        const float* p = part + (size_t)bh * 64 * Ss + (size_t)cq * 16 * Ss + j0 + j;
        float s = 0.f;
        #pragma unroll
        for (int c = 0; c < 16; c++) s += p[(size_t)c * Ss];
        wsum[cq][j] = s;
    }
    {   // V tile load
        const int j = tid >> 2, c0 = (tid & 3) * 16;
        const float* src = v + ((size_t)(b * Ss + j0 + j)) * Gg + h * DKk + c0;
        #pragma unroll
        for (int u = 0; u < 4; u++) {
            float4 f = *reinterpret_cast<const float4*>(src + u * 4);
            ts[j][c0 + 4*u]     = f.x; ts[j][c0 + 4*u + 1] = f.y;
            ts[j][c0 + 4*u + 2] = f.z; ts[j][c0 + 4*u + 3] = f.w;
        }
    }
    __syncthreads();
    if (tid < 64)
        winv_s[tid] = 1.0f / (((wsum[0][tid] + wsum[1][tid])
                             + (wsum[2][tid] + wsum[3][tid])));
    __syncthreads();

    const int d = tid >> 2, jj0 = (tid & 3) * 16;
    const size_t ob = (((size_t)bh) * DKk + d) * Ss + j0 + jj0;
    __half hbuf[16];
    #pragma unroll
    for (int u = 0; u < 16; u++)
        hbuf[u] = __float2half_rn(ts[jj0 + u][d] * winv_s[jj0 + u] * VSCALE);
    #pragma unroll
    for (int u = 0; u < 2; u++)
        *reinterpret_cast<uint4*>(tH + ob + u * 8) = reinterpret_cast<uint4*>(hbuf)[u];
}

// ---------------------------------------------------------------------------
// pv: Att = (P @ Vw^T)/4096, single fp16 MMA pass.  Writes att directly as
// bf16 hi/lo via staged coalesced epilogue (reuses mainloop smem).
// grid (32,8), 256 thr, smem 36864 B.
// ---------------------------------------------------------------------------
__global__ __launch_bounds__(256) void pv_wm_kernel(
    const __half* __restrict__ P, const __half* __restrict__ vt,
    __nv_bfloat16* __restrict__ atth, __nv_bfloat16* __restrict__ attl)
{
    extern __shared__ char sm[];
    const int PH = 0, VH = 18432;
    const int tid = threadIdx.x, lane = tid & 31, wid = tid >> 5;
    const int wm = wid >> 1, wn = wid & 1;
    const int bh = blockIdx.y, b = bh >> 2, h = bh & 3;
    const int i0 = blockIdx.x * 128;
    const int qr = lane >> 2, qc = lane & 3;

    const int prow = tid >> 1, phalf = tid & 1;
    const __half* pS = P + ((size_t)bh * Ss + i0 + prow) * Ss + phalf * 32;
    const unsigned pso = prow * 144 + phalf * 64;
    const int vrow = tid >> 2, vq = tid & 3;
    const __half* vS = vt + ((size_t)bh * DKk + vrow) * Ss + vq * 16;
    const unsigned vso = VH + vrow * 144 + vq * 32;

    const unsigned base = smem_u32(sm);
    const unsigned aoff = (wm * 32 + (lane & 15)) * 144 + ((lane >> 4) * 8) * 2;
    const unsigned boff = (wn * 32 + ((lane >> 4) & 1) * 8 + (lane & 7)) * 144
                        + (((lane >> 3) & 1) * 8) * 2;

    float acc[2][4][4] = {};
    uint4 rp[4], rv[2];

    #pragma unroll
    for (int u = 0; u < 4; u++) rp[u] = reinterpret_cast<const uint4*>(pS)[u];
    rv[0] = reinterpret_cast<const uint4*>(vS)[0];
    rv[1] = reinterpret_cast<const uint4*>(vS)[1];

    for (int c = 0; c < 64; c++) {
        #pragma unroll
        for (int u = 0; u < 4; u++)
            *reinterpret_cast<uint4*>(sm + PH + pso + u * 16) = rp[u];
        *reinterpret_cast<uint4*>(sm + vso)      = rv[0];
        *reinterpret_cast<uint4*>(sm + vso + 16) = rv[1];
        __syncthreads();

        if (c < 63) {
            const size_t go = (size_t)(c + 1) * 64;
            #pragma unroll
            for (int u = 0; u < 4; u++)
                rp[u] = reinterpret_cast<const uint4*>(pS + go)[u];
            rv[0] = reinterpret_cast<const uint4*>(vS + go)[0];
            rv[1] = reinterpret_cast<const uint4*>(vS + go)[1];
        }

        #pragma unroll
        for (int kk = 0; kk < 4; kk++) {
            unsigned aH[2][4], bH[2][4];
            #pragma unroll
            for (int mt = 0; mt < 2; mt++) {
                const unsigned ad = base + PH + aoff + mt * 2304 + kk * 32;
                ldsm4(aH[mt][0], aH[mt][1], aH[mt][2], aH[mt][3], ad);
            }
            #pragma unroll
            for (int g = 0; g < 2; g++) {
                const unsigned bd = base + VH + boff + g * 2304 + kk * 32;
                ldsm4(bH[g][0], bH[g][1], bH[g][2], bH[g][3], bd);
            }
            #pragma unroll
            for (int mt = 0; mt < 2; mt++)
                #pragma unroll
                for (int nt = 0; nt < 4; nt++)
                    mma_f16(acc[mt][nt], aH[mt], &bH[nt >> 1][(nt & 1) * 2]);
        }
        __syncthreads();
    }

    // staged bf16 hi/lo epilogue (reuses P/V smem; last loop iter ended with sync)
    __nv_bfloat16* sh = reinterpret_cast<__nv_bfloat16*>(sm);            // stride 72
    __nv_bfloat16* sl = reinterpret_cast<__nv_bfloat16*>(sm + 18432);
    #pragma unroll
    for (int mt = 0; mt < 2; mt++) {
        const int r0 = wm * 32 + mt * 16 + qr;
        #pragma unroll
        for (int nt = 0; nt < 4; nt++) {
            const int col = wn * 32 + nt * 8 + qc * 2;
            #pragma unroll
            for (int pr = 0; pr < 2; pr++) {
                unsigned hv, lv;
                split2(acc[mt][nt][pr * 2] * OSCALE,
                       acc[mt][nt][pr * 2 + 1] * OSCALE, hv, lv);
                *reinterpret_cast<unsigned*>(sh + (r0 + pr * 8) * 72 + col) = hv;
                *reinterpret_cast<unsigned*>(sl + (r0 + pr * 8) * 72 + col) = lv;
            }
        }
    }
    __syncthreads();
    #pragma unroll
    for (int ps = 0; ps < 4; ps++) {
        const int idx = ps * 2048 + tid * 8;
        const int row = idx >> 6, col = idx & 63;
        uint4 hv = *reinterpret_cast<const uint4*>(sh + row * 72 + col);
        uint4 lv = *reinterpret_cast<const uint4*>(sl + row * 72 + col);
        const size_t o = ((size_t)(b * Ss + i0 + row)) * Gg + h * DKk + col;
        *reinterpret_cast<uint4*>(atth + o) = hv;
        *reinterpret_cast<uint4*>(attl + o) = lv;
    }
}

// ---------------------------------------------------------------------------
extern "C" void kernel_launch(void* const* d_in, const int* in_sizes, int n_in,
                              void* d_out, int out_size)
{
    const float* x  = (const float*)d_in[0];
    const float* wq = (const float*)d_in[1];
    const float* bq = (const float*)d_in[2];
    const float* wk = (const float*)d_in[3];
    const float* bk = (const float*)d_in[4];
    const float* wv = (const float*)d_in[5];
    const float* bv = (const float*)d_in[6];
    const float* wo = (const float*)d_in[7];
    const float* bo = (const float*)d_in[8];
    float* out = (float*)d_out;

    __nv_bfloat16 *xh, *xl, *wh, *wl, *atth, *attl;
    __half *q16, *k16, *p, *vt;
    float *v, *part;
    cudaGetSymbolAddress((void**)&xh,  g_xh);   cudaGetSymbolAddress((void**)&xl,  g_xl);
    cudaGetSymbolAddress((void**)&wh,  g_wh);   cudaGetSymbolAddress((void**)&wl,  g_wl);
    cudaGetSymbolAddress((void**)&q16, g_q16);  cudaGetSymbolAddress((void**)&k16, g_k16);
    cudaGetSymbolAddress((void**)&v,   g_v);
    cudaGetSymbolAddress((void**)&p,   g_p);
    cudaGetSymbolAddress((void**)&part,g_part);
    cudaGetSymbolAddress((void**)&vt,  g_vt);
    cudaGetSymbolAddress((void**)&atth,g_atth); cudaGetSymbolAddress((void**)&attl,g_attl);

    const int SC_SMEM = 36864;
    const int PV_SMEM = 36864;
    const int TC_SMEM = 55552;
    cudaFuncSetAttribute(scores_wm_kernel, cudaFuncAttributeMaxDynamicSharedMemorySize, SC_SMEM);
    cudaFuncSetAttribute(pv_wm_kernel,     cudaFuncAttributeMaxDynamicSharedMemorySize, PV_SMEM);
    cudaFuncSetAttribute(gemm_qkv_kernel,  cudaFuncAttributeMaxDynamicSharedMemorySize, TC_SMEM);
    cudaFuncSetAttribute(gemm_out_kernel,  cudaFuncAttributeMaxDynamicSharedMemorySize, TC_SMEM);

    const int WN = Gg * Gg;

    // splits (2 launches)
    split_x_kernel<<<6144, 256>>>(x, xh, xl);
    split_w_kernel<<<dim3(64, 4), 256>>>(wq, wk, wv, wo, wh, wl);

    // QKV projections: one batched launch
    gemm_qkv_kernel<<<dim3(4, 64, 3), 256, TC_SMEM>>>(
        xh, xl, wh, wl, bq, bk, bv, q16, k16, v);

    // attention
    scores_wm_kernel<<<dim3(32, 32, 8), 256, SC_SMEM>>>(q16, k16, p, part);
    scale_v_t_kernel<<<dim3(64, 8), 256>>>(v, part, vt);
    pv_wm_kernel<<<dim3(32, 8), 256, PV_SMEM>>>(p, vt, atth, attl);

    // out projection (consumes bf16 hi/lo att directly)
    gemm_out_kernel<<<dim3(4, 64), 256, TC_SMEM>>>(atth, attl,
        wh + 3 * WN, wl + 3 * WN, bo, out);
}